// round 12
// baseline (speedup 1.0000x reference)
#include <cuda_runtime.h>
#include <cuda_bf16.h>
#include <math.h>
#include <stdint.h>

#define TT 256
#define BB 512
#define VV 50000
#define EE 300
#define HHH 100
#define KCRF 8
#define NN (TT*BB)

#define KPAD0 320
#define KPD2_0 160
#define KPAD1 224
#define KPD2_1 112

typedef unsigned long long ull;

// ---- helpers -------------------------------------------------------------------
__device__ __forceinline__ float sigf(float x) { return __frcp_rn(1.f + __expf(-x)); }
__device__ __forceinline__ float tanhfast(float x) { return __fmaf_rn(2.f, sigf(2.f*x), -1.f); }

__device__ __forceinline__ unsigned short bfbits(float a) {
    __nv_bfloat16 h = __float2bfloat16_rn(a);
    return *reinterpret_cast<unsigned short*>(&h);
}
__device__ __forceinline__ float bf2f(unsigned short u) {
    __nv_bfloat16 h = *reinterpret_cast<__nv_bfloat16*>(&u);
    return __bfloat162float(h);
}
__device__ __forceinline__ void bfsplit(float v, unsigned short &hi, unsigned short &lo) {
    hi = bfbits(v);
    lo = bfbits(v - bf2f(hi));
}

__device__ __forceinline__ uint32_t smem_u32(const void* p) {
    uint32_t a;
    asm("{ .reg .u64 t; cvta.to.shared.u64 t, %1; cvt.u32.u64 %0, t; }" : "=r"(a) : "l"(p));
    return a;
}
__device__ __forceinline__ void cpa16(uint32_t dst, const void* src) {
    asm volatile("cp.async.cg.shared.global [%0], [%1], 16;" :: "r"(dst), "l"(src));
}
__device__ __forceinline__ void cpa16z(uint32_t dst, const void* src, uint32_t ssz) {
    asm volatile("cp.async.cg.shared.global [%0], [%1], 16, %2;" :: "r"(dst), "l"(src), "r"(ssz));
}
#define CP_COMMIT() asm volatile("cp.async.commit_group;" ::: "memory")
#define CP_WAIT(n)  asm volatile("cp.async.wait_group %0;" :: "n"(n) : "memory")

// ---- mma.sync ------------------------------------------------------------------
__device__ __forceinline__ void mma16816(float d[4], const uint32_t a[4], const uint32_t b[2]) {
    asm volatile("mma.sync.aligned.m16n8k16.row.col.f32.bf16.bf16.f32 "
        "{%0,%1,%2,%3}, {%4,%5,%6,%7}, {%8,%9}, {%0,%1,%2,%3};"
        : "+f"(d[0]), "+f"(d[1]), "+f"(d[2]), "+f"(d[3])
        : "r"(a[0]), "r"(a[1]), "r"(a[2]), "r"(a[3]), "r"(b[0]), "r"(b[1]));
}
__device__ __forceinline__ void mma16816v(float d[4], const uint32_t a[4], uint32_t b0, uint32_t b1) {
    asm volatile("mma.sync.aligned.m16n8k16.row.col.f32.bf16.bf16.f32 "
        "{%0,%1,%2,%3}, {%4,%5,%6,%7}, {%8,%9}, {%0,%1,%2,%3};"
        : "+f"(d[0]), "+f"(d[1]), "+f"(d[2]), "+f"(d[3])
        : "r"(a[0]), "r"(a[1]), "r"(a[2]), "r"(a[3]), "r"(b0), "r"(b1));
}
__device__ __forceinline__ void mma1688(float d[4], uint32_t a0, uint32_t a1, uint32_t b0) {
    asm volatile("mma.sync.aligned.m16n8k8.row.col.f32.bf16.bf16.f32 "
        "{%0,%1,%2,%3}, {%4,%5}, {%6}, {%0,%1,%2,%3};"
        : "+f"(d[0]), "+f"(d[1]), "+f"(d[2]), "+f"(d[3])
        : "r"(a0), "r"(a1), "r"(b0));
}

// ---- scratch -------------------------------------------------------------------
__device__ uint32_t g_Bh0[800*KPD2_0];
__device__ uint32_t g_Bl0[800*KPD2_0];
__device__ uint32_t g_Bh1[800*KPD2_1];
__device__ uint32_t g_Bl1[800*KPD2_1];
__device__ float    g_b0[800];
__device__ float    g_b1[800];
__device__ uint32_t g_Wpk_h[2*400*56];
__device__ uint32_t g_Wpk_l[2*400*56];
__device__ uint32_t g_A0h[(size_t)VV*KPD2_0];
__device__ uint32_t g_A0l[(size_t)VV*KPD2_0];
__device__ uint32_t g_A1h[(size_t)NN*KPD2_1];
__device__ uint32_t g_A1l[(size_t)NN*KPD2_1];
__device__ float    g_projemb[(size_t)VV*800];
__device__ float    g_xp1[(size_t)NN*800];
__device__ float    g_h2[(size_t)NN*200];
__device__ float    g_em[(size_t)NN*KCRF];
__device__ unsigned char g_hist[(size_t)(TT-1)*BB*KCRF];
__device__ float    g_pl[BB];

// ---- weight prep (input-proj weights for GEMM) ---------------------------------
__global__ void prep_kernel(
    const float* __restrict__ wih0f, const float* __restrict__ wih0b,
    const float* __restrict__ bih0f, const float* __restrict__ bhh0f,
    const float* __restrict__ bih0b, const float* __restrict__ bhh0b,
    const float* __restrict__ wih1f, const float* __restrict__ wih1b,
    const float* __restrict__ bih1f, const float* __restrict__ bhh1f,
    const float* __restrict__ bih1b, const float* __restrict__ bhh1b)
{
    int i = blockIdx.x*256 + threadIdx.x;
    if (i < 800*KPD2_0) {
        int n = i / KPD2_0, kk = i % KPD2_0;
        int k0 = 2*kk, k1 = 2*kk + 1;
        float v0 = (k0 < EE) ? ((n < 400) ? wih0f[n*EE + k0] : wih0b[(n-400)*EE + k0]) : 0.f;
        float v1 = (k1 < EE) ? ((n < 400) ? wih0f[n*EE + k1] : wih0b[(n-400)*EE + k1]) : 0.f;
        unsigned short h0, l0, h1, l1;
        bfsplit(v0, h0, l0); bfsplit(v1, h1, l1);
        g_Bh0[i] = (uint32_t)h0 | ((uint32_t)h1 << 16);
        g_Bl0[i] = (uint32_t)l0 | ((uint32_t)l1 << 16);
    } else if (i < 800*KPD2_0 + 800*KPD2_1) {
        int j = i - 800*KPD2_0;
        int n = j / KPD2_1, kk = j % KPD2_1;
        int k0 = 2*kk, k1 = 2*kk + 1;
        float v0 = (k0 < 200) ? ((n < 400) ? wih1f[n*200 + k0] : wih1b[(n-400)*200 + k0]) : 0.f;
        float v1 = (k1 < 200) ? ((n < 400) ? wih1f[n*200 + k1] : wih1b[(n-400)*200 + k1]) : 0.f;
        unsigned short h0, l0, h1, l1;
        bfsplit(v0, h0, l0); bfsplit(v1, h1, l1);
        g_Bh1[j] = (uint32_t)h0 | ((uint32_t)h1 << 16);
        g_Bl1[j] = (uint32_t)l0 | ((uint32_t)l1 << 16);
    } else if (i < 800*KPD2_0 + 800*KPD2_1 + 800) {
        int n = i - (800*KPD2_0 + 800*KPD2_1);
        g_b0[n] = (n < 400) ? (bih0f[n] + bhh0f[n]) : (bih0b[n-400] + bhh0b[n-400]);
    } else if (i < 800*KPD2_0 + 800*KPD2_1 + 1600) {
        int n = i - (800*KPD2_0 + 800*KPD2_1 + 800);
        g_b1[n] = (n < 400) ? (bih1f[n] + bhh1f[n]) : (bih1b[n-400] + bhh1b[n-400]);
    }
}

// ---- whh pack with gate-row permutation ----------------------------------------
__global__ void prep_whh(const float* __restrict__ whhf, const float* __restrict__ whhb,
                         uint32_t* __restrict__ Wh, uint32_t* __restrict__ Wl)
{
    int i = blockIdx.x*256 + threadIdx.x;
    if (i >= 2*400*56) return;
    int d = i / (400*56);
    int rem = i - d*(400*56);
    int gp = rem / 56, w = rem % 56;
    int wp = gp >> 4, r = gp & 15;
    int type = r >> 2, hh = wp*4 + (r & 3);
    int srow = type*100 + hh;
    const float* W = d ? whhb : whhf;
    int k0 = 2*w, k1 = 2*w + 1;
    float v0 = (k0 < 100) ? W[srow*100 + k0] : 0.f;
    float v1 = (k1 < 100) ? W[srow*100 + k1] : 0.f;
    unsigned short h0b, l0b, h1b, l1b;
    bfsplit(v0, h0b, l0b); bfsplit(v1, h1b, l1b);
    Wh[i] = (uint32_t)h0b | ((uint32_t)h1b << 16);
    Wl[i] = (uint32_t)l0b | ((uint32_t)l1b << 16);
}

// ---- A split pass (emb only) ---------------------------------------------------
__global__ void split_a(const float* __restrict__ A, uint32_t* __restrict__ Ah,
                        uint32_t* __restrict__ Al, int M, int K, int kpd2)
{
    size_t i = (size_t)blockIdx.x*256 + threadIdx.x;
    if (i >= (size_t)M*kpd2) return;
    int kk = (int)(i % kpd2);
    size_t r = i / kpd2;
    int k0 = 2*kk, k1 = 2*kk + 1;
    float v0 = (k0 < K) ? A[r*K + k0] : 0.f;
    float v1 = (k1 < K) ? A[r*K + k1] : 0.f;
    unsigned short h0, l0, h1, l1;
    bfsplit(v0, h0, l0); bfsplit(v1, h1, l1);
    Ah[i] = (uint32_t)h0 | ((uint32_t)h1 << 16);
    Al[i] = (uint32_t)l0 | ((uint32_t)l1 << 16);
}

// ---- zero padding cols 100..111 of the layer-1 A operand -----------------------
__global__ void zero_tail(uint32_t* __restrict__ Ah, uint32_t* __restrict__ Al)
{
    size_t i = (size_t)blockIdx.x*256 + threadIdx.x;
    if (i >= (size_t)NN*12) return;
    size_t row = i / 12;
    int cc = 100 + (int)(i % 12);
    Ah[row*112 + cc] = 0;
    Al[row*112 + cc] = 0;
}

// ---- HMMA bf16 3-term GEMM: block 64x160, 2 blocks/SM --------------------------
#define AS_OFF(bf,s,r,q) ((((bf)*2 + (s))*64 + (r))*20 + (q))
#define BS_OFF(bf,s,r,q) (5120 + (((bf)*2 + (s))*160 + (r))*20 + (q))
#define GSM_BYTES (17920*4)

__global__ void __launch_bounds__(256, 2) mma_gemm(
    const uint32_t* __restrict__ Ah, const uint32_t* __restrict__ Al,
    const uint32_t* __restrict__ Bh, const uint32_t* __restrict__ Bl,
    const float* __restrict__ bias, float* __restrict__ C,
    int M, int kpd2, int nc)
{
    extern __shared__ uint32_t s32[];
    const uint32_t sb = smem_u32(s32);
    const int tid = threadIdx.x;
    const int bm  = blockIdx.y * 64;
    const int bn0 = blockIdx.x * 160;
    const int warp = tid >> 5, lane = tid & 31;
    const int wm = (warp & 1) * 32;
    const int wn = (warp >> 1) * 40;
    const int g = lane >> 2, tig = lane & 3;

    float acc[2][5][4];
    #pragma unroll
    for (int mf = 0; mf < 2; mf++)
        #pragma unroll
        for (int nf = 0; nf < 5; nf++)
            #pragma unroll
            for (int c = 0; c < 4; c++) acc[mf][nf][c] = 0.f;

    auto stageA = [&](int ci, int bf) {
        #pragma unroll
        for (int j = 0; j < 2; j++) {
            int idx = tid + 256*j;          // 0..511
            int s = idx >> 8;               // 256 16B-chunks per split
            int r = (idx >> 2) & 63;
            int q = idx & 3;
            const uint32_t* base = s ? Al : Ah;
            int row = bm + r;
            const uint32_t* src = (row < M) ? (base + (size_t)row*kpd2 + ci*16 + q*4) : base;
            cpa16z(sb + 4*AS_OFF(bf, s, r, q*4), src, (row < M) ? 16u : 0u);
        }
    };
    auto stageB = [&](int ci, int bf) {
        #pragma unroll
        for (int j = 0; j < 5; j++) {
            int idx = tid + 256*j;
            int s = idx / 640;
            int rem = idx - s*640;
            int r = rem >> 2;
            int q = rem & 3;
            const uint32_t* base = s ? Bl : Bh;
            cpa16(sb + 4*BS_OFF(bf, s, r, q*4), base + (size_t)(bn0 + r)*kpd2 + ci*16 + q*4);
        }
    };

    stageA(0, 0); stageB(0, 0); CP_COMMIT();
    stageA(1, 1); stageB(1, 1); CP_COMMIT();

    for (int ci = 0; ci < nc; ci++) {
        const int bf = ci & 1;
        if (ci + 1 < nc) { CP_WAIT(1); } else { CP_WAIT(0); }
        __syncthreads();

        #pragma unroll
        for (int ks = 0; ks < 2; ks++) {
            const int kb = 8*ks;
            uint32_t aH[2][4], aL[2][4], bH[5][2], bL[5][2];
            #pragma unroll
            for (int mf = 0; mf < 2; mf++) {
                int r0 = wm + mf*16 + g;
                aH[mf][0] = s32[AS_OFF(bf,0,r0,   kb+tig)];
                aH[mf][1] = s32[AS_OFF(bf,0,r0+8, kb+tig)];
                aH[mf][2] = s32[AS_OFF(bf,0,r0,   kb+4+tig)];
                aH[mf][3] = s32[AS_OFF(bf,0,r0+8, kb+4+tig)];
                aL[mf][0] = s32[AS_OFF(bf,1,r0,   kb+tig)];
                aL[mf][1] = s32[AS_OFF(bf,1,r0+8, kb+tig)];
                aL[mf][2] = s32[AS_OFF(bf,1,r0,   kb+4+tig)];
                aL[mf][3] = s32[AS_OFF(bf,1,r0+8, kb+4+tig)];
            }
            #pragma unroll
            for (int nf = 0; nf < 5; nf++) {
                int n = wn + nf*8 + g;
                bH[nf][0] = s32[BS_OFF(bf,0,n, kb+tig)];
                bH[nf][1] = s32[BS_OFF(bf,0,n, kb+4+tig)];
                bL[nf][0] = s32[BS_OFF(bf,1,n, kb+tig)];
                bL[nf][1] = s32[BS_OFF(bf,1,n, kb+4+tig)];
            }
            #pragma unroll
            for (int mf = 0; mf < 2; mf++)
                #pragma unroll
                for (int nf = 0; nf < 5; nf++) {
                    mma16816(acc[mf][nf], aH[mf], bH[nf]);
                    mma16816(acc[mf][nf], aH[mf], bL[nf]);
                    mma16816(acc[mf][nf], aL[mf], bH[nf]);
                }
        }

        if (ci + 2 < nc) {
            __syncthreads();
            stageA(ci + 2, bf); stageB(ci + 2, bf); CP_COMMIT();
        }
    }

    #pragma unroll
    for (int mf = 0; mf < 2; mf++) {
        int r0 = bm + wm + mf*16 + g;
        #pragma unroll
        for (int nf = 0; nf < 5; nf++) {
            int col = bn0 + wn + nf*8 + 2*tig;
            float b0v = bias[col], b1v = bias[col + 1];
            if (r0 < M) {
                float2 o = make_float2(acc[mf][nf][0] + b0v, acc[mf][nf][1] + b1v);
                *(float2*)&C[(size_t)r0*800 + col] = o;
            }
            if (r0 + 8 < M) {
                float2 o = make_float2(acc[mf][nf][2] + b0v, acc[mf][nf][3] + b1v);
                *(float2*)&C[(size_t)(r0 + 8)*800 + col] = o;
            }
        }
    }
}

// ---- HMMA persistent BiLSTM (R10 version, unchanged) ---------------------------
__global__ void __launch_bounds__(800, 1) lstm_layer(
    const float* __restrict__ xsrc, const int* __restrict__ sentence,
    const uint32_t* __restrict__ Wpkh, const uint32_t* __restrict__ Wpkl,
    float* __restrict__ hout, uint32_t* __restrict__ Aoh, uint32_t* __restrict__ Aol,
    int mode)
{
    __shared__ uint32_t Hh[2][448];
    __shared__ uint32_t Hl[2][448];
    __shared__ int tok_s[2][8];
    const int tid  = threadIdx.x;
    const int warp = tid >> 5, lane = tid & 31;
    const int qq = lane & 3, nn = lane >> 2;
    const int dir = blockIdx.x >> 6;
    const int b0  = (blockIdx.x & 63) * 8;
    const int xofs = dir * 400;

    const uint32_t* Wbh = Wpkh + dir*22400;
    const uint32_t* Wbl = Wpkl + dir*22400;
    const int g0 = warp*16 + nn;
    uint32_t Ahr[26], Alr[26];
    #pragma unroll
    for (int ks = 0; ks < 6; ks++) {
        Ahr[ks*4+0] = Wbh[ g0    *56 + ks*8 + qq];
        Ahr[ks*4+1] = Wbh[(g0+8)*56 + ks*8 + qq];
        Ahr[ks*4+2] = Wbh[ g0    *56 + ks*8 + 4 + qq];
        Ahr[ks*4+3] = Wbh[(g0+8)*56 + ks*8 + 4 + qq];
        Alr[ks*4+0] = Wbl[ g0    *56 + ks*8 + qq];
        Alr[ks*4+1] = Wbl[(g0+8)*56 + ks*8 + qq];
        Alr[ks*4+2] = Wbl[ g0    *56 + ks*8 + 4 + qq];
        Alr[ks*4+3] = Wbl[(g0+8)*56 + ks*8 + 4 + qq];
    }
    Ahr[24] = Wbh[g0*56 + 48 + qq];  Ahr[25] = Wbh[(g0+8)*56 + 48 + qq];
    Alr[24] = Wbl[g0*56 + 48 + qq];  Alr[25] = Wbl[(g0+8)*56 + 48 + qq];

    for (int i = tid; i < 448; i += 800) {
        Hh[0][i] = 0; Hh[1][i] = 0; Hl[0][i] = 0; Hl[1][i] = 0;
    }

    const int rr  = nn;
    const int hh  = warp*4 + (rr & 3);
    const int o1  = (rr < 4) ? 0 : 100;
    const int h0e = hh & ~1;
    const int wks = h0e >> 4, wkq = (h0e & 7) >> 1, wkr = (h0e >> 3) & 1;
    const int bsel = ((rr & 1) == 0) ? (2*qq) : (2*qq + 1);
    const int widx = ((wks*4 + wkq)*8 + bsel)*2 + wkr;
    float c0 = 0.f, c1 = 0.f;

    for (int step = 0; step < TT; step++) {
        const int t = dir ? (TT - 1 - step) : step;
        const int cur = step & 1;
        if (mode == 0 && tid < 8) tok_s[cur][tid] = sentence[t*BB + b0 + tid];
        __syncthreads();

        const float *xr0, *xr1;
        if (mode == 0) {
            xr0 = xsrc + (size_t)tok_s[cur][2*qq]*800 + xofs + hh;
            xr1 = xsrc + (size_t)tok_s[cur][2*qq + 1]*800 + xofs + hh;
        } else {
            xr0 = xsrc + ((size_t)t*BB + b0 + 2*qq)*800 + xofs + hh;
            xr1 = xr0 + 800;
        }
        float xa0 = xr0[o1],       xa1 = xr1[o1];
        float xg0 = xr0[o1 + 200], xg1 = xr1[o1 + 200];

        const uint32_t* HhR = Hh[cur];
        const uint32_t* HlR = Hl[cur];
        float d4[4] = {0.f, 0.f, 0.f, 0.f};
        #pragma unroll
        for (int ks = 0; ks < 6; ks++) {
            uint2 bh = *(const uint2*)&HhR[(ks*32 + qq*8 + nn)*2];
            uint2 bl = *(const uint2*)&HlR[(ks*32 + qq*8 + nn)*2];
            mma16816v(d4, &Ahr[ks*4], bh.x, bh.y);
            mma16816v(d4, &Alr[ks*4], bh.x, bh.y);
            mma16816v(d4, &Ahr[ks*4], bl.x, bl.y);
        }
        {
            uint32_t bh6 = HhR[(192 + qq*8 + nn)*2];
            uint32_t bl6 = HlR[(192 + qq*8 + nn)*2];
            mma1688(d4, Ahr[24], Ahr[25], bh6);
            mma1688(d4, Alr[24], Alr[25], bh6);
            mma1688(d4, Ahr[24], Ahr[25], bl6);
        }

        d4[0] += xa0; d4[1] += xa1; d4[2] += xg0; d4[3] += xg1;
        float s0 = __shfl_xor_sync(0xFFFFFFFFu, d4[0], 16);
        float s1 = __shfl_xor_sync(0xFFFFFFFFu, d4[1], 16);
        float s2 = __shfl_xor_sync(0xFFFFFFFFu, d4[2], 16);
        float s3 = __shfl_xor_sync(0xFFFFFFFFu, d4[3], 16);

        if (lane < 16) {
            float iv0 = sigf(d4[0]), fv0 = sigf(s0), gv0 = tanhfast(d4[2]), ov0 = sigf(s2);
            float iv1 = sigf(d4[1]), fv1 = sigf(s1), gv1 = tanhfast(d4[3]), ov1 = sigf(s3);
            c0 = fv0*c0 + iv0*gv0;
            c1 = fv1*c1 + iv1*gv1;
            float hv0 = ov0 * tanhfast(c0);
            float hv1 = ov1 * tanhfast(c1);

            float p0 = __shfl_xor_sync(0x0000FFFFu, hv0, 4);
            float p1 = __shfl_xor_sync(0x0000FFFFu, hv1, 4);
            bool evenr = ((rr & 1) == 0);
            float vlo = evenr ? hv0 : p1;
            float vhi = evenr ? p0  : hv1;
            unsigned short lhh, lhl, hhh, hhl;
            bfsplit(vlo, lhh, lhl);
            bfsplit(vhi, hhh, hhl);
            uint32_t wh  = (uint32_t)lhh | ((uint32_t)hhh << 16);
            uint32_t wl2 = (uint32_t)lhl | ((uint32_t)hhl << 16);
            const int wrb = cur ^ 1;
            Hh[wrb][widx] = wh;
            Hl[wrb][widx] = wl2;

            if (mode == 0) {
                size_t row = (size_t)t*BB + b0 + bsel;
                size_t col = (size_t)dir*50 + (h0e >> 1);
                Aoh[row*112 + col] = wh;
                Aol[row*112 + col] = wl2;
            } else {
                hout[((size_t)t*BB + b0 + 2*qq)*200 + dir*100 + hh]     = hv0;
                hout[((size_t)t*BB + b0 + 2*qq + 1)*200 + dir*100 + hh] = hv1;
            }
        }
    }
}

// ---- emissions -----------------------------------------------------------------
__global__ void __launch_bounds__(256) em_kernel(
    const float* __restrict__ h2, const float* __restrict__ wl,
    const float* __restrict__ bl, float* __restrict__ em)
{
    __shared__ float wls[1600];
    __shared__ float bls[8];
    int tid = threadIdx.x;
    for (int i = tid; i < 1600; i += 256) wls[i] = wl[i];
    if (tid < 8) bls[tid] = bl[tid];
    __syncthreads();
    int warp = tid >> 5, lane = tid & 31;
    size_t row = (size_t)blockIdx.x*8 + warp;
    float acc[8] = {0.f,0.f,0.f,0.f,0.f,0.f,0.f,0.f};
    const float* hr = h2 + row*200;
    #pragma unroll
    for (int i = 0; i < 7; i++) {
        int k = lane + i*32;
        if (k < 200) {
            float x = hr[k];
            #pragma unroll
            for (int gg = 0; gg < 8; gg++) acc[gg] += x * wls[gg*200 + k];
        }
    }
    #pragma unroll
    for (int gg = 0; gg < 8; gg++) {
        float v = acc[gg];
        #pragma unroll
        for (int o = 16; o > 0; o >>= 1) v += __shfl_xor_sync(0xffffffffu, v, o);
        if (lane == 0) em[row*8 + gg] = v + bls[gg];
    }
}

// ---- CRF forward ---------------------------------------------------------------
__global__ void __launch_bounds__(256) crf_fwd(
    const float* __restrict__ em, const int* __restrict__ tags,
    const float* __restrict__ start_t, const float* __restrict__ end_t,
    const float* __restrict__ trans, float* __restrict__ pl)
{
    int tid = blockIdx.x*256 + threadIdx.x;
    int b = tid >> 3, k = tid & 7;
    float trcol[8];
    #pragma unroll
    for (int kk = 0; kk < 8; kk++) trcol[kk] = trans[kk*8 + k];

    float score = start_t[k] + em[(size_t)b*8 + k];

    float nump = 0.f;
    for (int t = 1 + k; t < TT; t += 8) {
        int tp = tags[(t-1)*BB + b];
        int tc = tags[t*BB + b];
        nump += trans[tp*8 + tc] + em[((size_t)t*BB + b)*8 + tc];
    }
    if (k == 0) {
        int t0 = tags[b];
        nump += start_t[t0] + em[(size_t)b*8 + t0] + end_t[tags[(TT-1)*BB + b]];
    }

    for (int t = 1; t < TT; t++) {
        float e = em[((size_t)t*BB + b)*8 + k];
        float v[8];
        float m = -3.4e38f;
        #pragma unroll
        for (int kk = 0; kk < 8; kk++) {
            float s = __shfl_sync(0xffffffffu, score, kk, 8);
            v[kk] = s + trcol[kk];
            m = fmaxf(m, v[kk]);
        }
        float ss = 0.f;
        #pragma unroll
        for (int kk = 0; kk < 8; kk++) ss += expf(v[kk] - m);
        score = m + logf(ss) + e;
    }

    float v = score + end_t[k];
    float m = v;
    #pragma unroll
    for (int kk = 0; kk < 8; kk++) m = fmaxf(m, __shfl_sync(0xffffffffu, v, kk, 8));
    float ex = expf(v - m);
    float ssum = 0.f;
    #pragma unroll
    for (int kk = 0; kk < 8; kk++) ssum += __shfl_sync(0xffffffffu, ex, kk, 8);
    float denom = m + logf(ssum);

    float nsum = 0.f;
    #pragma unroll
    for (int kk = 0; kk < 8; kk++) nsum += __shfl_sync(0xffffffffu, nump, kk, 8);
    if (k == 0) pl[b] = nsum - denom;
}

// ---- Viterbi -------------------------------------------------------------------
__global__ void __launch_bounds__(256) viterbi_k(
    const float* __restrict__ em, const float* __restrict__ start_t,
    const float* __restrict__ end_t, const float* __restrict__ trans,
    unsigned char* __restrict__ hist, float* __restrict__ dec)
{
    int tid = blockIdx.x*256 + threadIdx.x;
    int b = tid >> 3, k = tid & 7;
    float trcol[8];
    #pragma unroll
    for (int kk = 0; kk < 8; kk++) trcol[kk] = trans[kk*8 + k];

    float score = start_t[k] + em[(size_t)b*8 + k];
    for (int t = 1; t < TT; t++) {
        float e = em[((size_t)t*BB + b)*8 + k];
        float best = -3.4e38f;
        int arg = 0;
        #pragma unroll
        for (int kk = 0; kk < 8; kk++) {
            float s = __shfl_sync(0xffffffffu, score, kk, 8) + trcol[kk];
            if (s > best) { best = s; arg = kk; }
        }
        hist[((size_t)(t-1)*BB + b)*8 + k] = (unsigned char)arg;
        score = best + e;
    }
    float v = score + end_t[k];
    float best = -3.4e38f;
    int arg = 0;
    #pragma unroll
    for (int kk = 0; kk < 8; kk++) {
        float s = __shfl_sync(0xffffffffu, v, kk, 8);
        if (s > best) { best = s; arg = kk; }
    }
    __syncwarp();
    if (k == 0) {
        int nxt = arg;
        dec[(size_t)(TT-1)*BB + b] = (float)nxt;
        for (int i = TT - 2; i >= 0; i--) {
            nxt = hist[((size_t)i*BB + b)*8 + nxt];
            dec[(size_t)i*BB + b] = (float)nxt;
        }
    }
}

// ---- deterministic loss reduction ----------------------------------------------
__global__ void loss_reduce(const float* __restrict__ pl, float* __restrict__ out)
{
    __shared__ float s[512];
    int tid = threadIdx.x;
    s[tid] = pl[tid];
    __syncthreads();
    for (int ofs = 256; ofs > 0; ofs >>= 1) {
        if (tid < ofs) s[tid] += s[tid + ofs];
        __syncthreads();
    }
    if (tid == 0) out[0] = s[0];
}

// ---- host launch ---------------------------------------------------------------
extern "C" void kernel_launch(void* const* d_in, const int* in_sizes, int n_in,
                              void* d_out, int out_size)
{
    const int*   sentence = (const int*)d_in[0];
    const int*   tags     = (const int*)d_in[1];
    const float* emb      = (const float*)d_in[3];
    const float* wih0f = (const float*)d_in[4];
    const float* whh0f = (const float*)d_in[5];
    const float* bih0f = (const float*)d_in[6];
    const float* bhh0f = (const float*)d_in[7];
    const float* wih0b = (const float*)d_in[8];
    const float* whh0b = (const float*)d_in[9];
    const float* bih0b = (const float*)d_in[10];
    const float* bhh0b = (const float*)d_in[11];
    const float* wih1f = (const float*)d_in[12];
    const float* whh1f = (const float*)d_in[13];
    const float* bih1f = (const float*)d_in[14];
    const float* bhh1f = (const float*)d_in[15];
    const float* wih1b = (const float*)d_in[16];
    const float* whh1b = (const float*)d_in[17];
    const float* bih1b = (const float*)d_in[18];
    const float* bhh1b = (const float*)d_in[19];
    const float* wl      = (const float*)d_in[20];
    const float* bl      = (const float*)d_in[21];
    const float* start_t = (const float*)d_in[22];
    const float* end_t   = (const float*)d_in[23];
    const float* trans   = (const float*)d_in[24];
    float* out = (float*)d_out;

    void* p;
    cudaGetSymbolAddress(&p, g_Bh0);     uint32_t* pBh0 = (uint32_t*)p;
    cudaGetSymbolAddress(&p, g_Bl0);     uint32_t* pBl0 = (uint32_t*)p;
    cudaGetSymbolAddress(&p, g_Bh1);     uint32_t* pBh1 = (uint32_t*)p;
    cudaGetSymbolAddress(&p, g_Bl1);     uint32_t* pBl1 = (uint32_t*)p;
    cudaGetSymbolAddress(&p, g_b0);      float* pB0   = (float*)p;
    cudaGetSymbolAddress(&p, g_b1);      float* pB1   = (float*)p;
    cudaGetSymbolAddress(&p, g_Wpk_h);   uint32_t* pWph = (uint32_t*)p;
    cudaGetSymbolAddress(&p, g_Wpk_l);   uint32_t* pWpl = (uint32_t*)p;
    cudaGetSymbolAddress(&p, g_A0h);     uint32_t* pA0h = (uint32_t*)p;
    cudaGetSymbolAddress(&p, g_A0l);     uint32_t* pA0l = (uint32_t*)p;
    cudaGetSymbolAddress(&p, g_A1h);     uint32_t* pA1h = (uint32_t*)p;
    cudaGetSymbolAddress(&p, g_A1l);     uint32_t* pA1l = (uint32_t*)p;
    cudaGetSymbolAddress(&p, g_projemb); float* pProj = (float*)p;
    cudaGetSymbolAddress(&p, g_xp1);     float* pXp1  = (float*)p;
    cudaGetSymbolAddress(&p, g_h2);      float* pH2   = (float*)p;
    cudaGetSymbolAddress(&p, g_em);      float* pEm   = (float*)p;
    cudaGetSymbolAddress(&p, g_hist);    unsigned char* pHist = (unsigned char*)p;
    cudaGetSymbolAddress(&p, g_pl);      float* pPl   = (float*)p;

    cudaFuncSetAttribute(mma_gemm, cudaFuncAttributeMaxDynamicSharedMemorySize, GSM_BYTES);

    prep_kernel<<<(800*KPD2_0 + 800*KPD2_1 + 1600 + 255)/256, 256>>>(
        wih0f, wih0b, bih0f, bhh0f, bih0b, bhh0b,
        wih1f, wih1b, bih1f, bhh1f, bih1b, bhh1b);

    prep_whh<<<(2*400*56 + 255)/256, 256>>>(whh0f, whh0b, pWph, pWpl);

    {
        size_t tot = (size_t)VV*KPD2_0;
        split_a<<<(unsigned)((tot + 255)/256), 256>>>(emb, pA0h, pA0l, VV, EE, KPD2_0);
    }
    zero_tail<<<(unsigned)(((size_t)NN*12 + 255)/256), 256>>>(pA1h, pA1l);

    mma_gemm<<<dim3(5, (VV + 63)/64), 256, GSM_BYTES>>>(
        pA0h, pA0l, pBh0, pBl0, pB0, pProj, VV, KPD2_0, KPAD0/32);

    lstm_layer<<<128, 800>>>(pProj, sentence, pWph, pWpl, pH2, pA1h, pA1l, 0);

    prep_whh<<<(2*400*56 + 255)/256, 256>>>(whh1f, whh1b, pWph, pWpl);

    mma_gemm<<<dim3(5, NN/64), 256, GSM_BYTES>>>(
        pA1h, pA1l, pBh1, pBl1, pB1, pXp1, NN, KPD2_1, KPAD1/32);

    lstm_layer<<<128, 800>>>(pXp1, (const int*)0, pWph, pWpl, pH2, pA1h, pA1l, 1);

    em_kernel<<<NN/8, 256>>>(pH2, wl, bl, pEm);

    crf_fwd<<<BB*KCRF/256, 256>>>(pEm, tags, start_t, end_t, trans, pPl);

    viterbi_k<<<BB*KCRF/256, 256>>>(pEm, start_t, end_t, trans, pHist, out + 1);

    loss_reduce<<<1, 512>>>(pPl, out);
}

// round 13
// speedup vs baseline: 1.0196x; 1.0196x over previous
#include <cuda_runtime.h>
#include <cuda_bf16.h>
#include <math.h>
#include <stdint.h>

#define TT 256
#define BB 512
#define VV 50000
#define EE 300
#define HHH 100
#define KCRF 8
#define NN (TT*BB)

#define KPAD0 320
#define KPD2_0 160
#define KPAD1 224
#define KPD2_1 112

typedef unsigned long long ull;

// ---- helpers -------------------------------------------------------------------
__device__ __forceinline__ float sigf(float x) { return __frcp_rn(1.f + __expf(-x)); }
__device__ __forceinline__ float tanhfast(float x) { return __fmaf_rn(2.f, sigf(2.f*x), -1.f); }

__device__ __forceinline__ unsigned short bfbits(float a) {
    __nv_bfloat16 h = __float2bfloat16_rn(a);
    return *reinterpret_cast<unsigned short*>(&h);
}
__device__ __forceinline__ float bf2f(unsigned short u) {
    __nv_bfloat16 h = *reinterpret_cast<__nv_bfloat16*>(&u);
    return __bfloat162float(h);
}
__device__ __forceinline__ void bfsplit(float v, unsigned short &hi, unsigned short &lo) {
    hi = bfbits(v);
    lo = bfbits(v - bf2f(hi));
}

__device__ __forceinline__ uint32_t smem_u32(const void* p) {
    uint32_t a;
    asm("{ .reg .u64 t; cvta.to.shared.u64 t, %1; cvt.u32.u64 %0, t; }" : "=r"(a) : "l"(p));
    return a;
}
__device__ __forceinline__ void cpa16(uint32_t dst, const void* src) {
    asm volatile("cp.async.cg.shared.global [%0], [%1], 16;" :: "r"(dst), "l"(src));
}
__device__ __forceinline__ void cpa16z(uint32_t dst, const void* src, uint32_t ssz) {
    asm volatile("cp.async.cg.shared.global [%0], [%1], 16, %2;" :: "r"(dst), "l"(src), "r"(ssz));
}
#define CP_COMMIT() asm volatile("cp.async.commit_group;" ::: "memory")
#define CP_WAIT(n)  asm volatile("cp.async.wait_group %0;" :: "n"(n) : "memory")

// ---- mma.sync ------------------------------------------------------------------
__device__ __forceinline__ void mma16816(float d[4], const uint32_t a[4], const uint32_t b[2]) {
    asm volatile("mma.sync.aligned.m16n8k16.row.col.f32.bf16.bf16.f32 "
        "{%0,%1,%2,%3}, {%4,%5,%6,%7}, {%8,%9}, {%0,%1,%2,%3};"
        : "+f"(d[0]), "+f"(d[1]), "+f"(d[2]), "+f"(d[3])
        : "r"(a[0]), "r"(a[1]), "r"(a[2]), "r"(a[3]), "r"(b[0]), "r"(b[1]));
}
__device__ __forceinline__ void mma16816v(float d[4], const uint32_t a[4], uint32_t b0, uint32_t b1) {
    asm volatile("mma.sync.aligned.m16n8k16.row.col.f32.bf16.bf16.f32 "
        "{%0,%1,%2,%3}, {%4,%5,%6,%7}, {%8,%9}, {%0,%1,%2,%3};"
        : "+f"(d[0]), "+f"(d[1]), "+f"(d[2]), "+f"(d[3])
        : "r"(a[0]), "r"(a[1]), "r"(a[2]), "r"(a[3]), "r"(b0), "r"(b1));
}
__device__ __forceinline__ void mma1688(float d[4], uint32_t a0, uint32_t a1, uint32_t b0) {
    asm volatile("mma.sync.aligned.m16n8k8.row.col.f32.bf16.bf16.f32 "
        "{%0,%1,%2,%3}, {%4,%5}, {%6}, {%0,%1,%2,%3};"
        : "+f"(d[0]), "+f"(d[1]), "+f"(d[2]), "+f"(d[3])
        : "r"(a0), "r"(a1), "r"(b0));
}

// ---- scratch -------------------------------------------------------------------
__device__ uint32_t g_Bh0[800*KPD2_0];
__device__ uint32_t g_Bl0[800*KPD2_0];
__device__ uint32_t g_Bh1[800*KPD2_1];
__device__ uint32_t g_Bl1[800*KPD2_1];
__device__ float    g_b0[800];
__device__ float    g_b1[800];
__device__ uint32_t g_Wpk_h[2*400*56];
__device__ uint32_t g_Wpk_l[2*400*56];
__device__ uint32_t g_A0h[(size_t)VV*KPD2_0];
__device__ uint32_t g_A0l[(size_t)VV*KPD2_0];
__device__ uint32_t g_A1h[(size_t)NN*KPD2_1];
__device__ uint32_t g_A1l[(size_t)NN*KPD2_1];
__device__ float    g_projemb[(size_t)VV*800];
__device__ float    g_h1[(size_t)NN*200];
__device__ float    g_xp1[(size_t)NN*800];
__device__ float    g_h2[(size_t)NN*200];
__device__ float    g_em[(size_t)NN*KCRF];
__device__ unsigned char g_hist[(size_t)(TT-1)*BB*KCRF];
__device__ float    g_pl[BB];

// ---- weight prep (input-proj weights for GEMM) ---------------------------------
__global__ void prep_kernel(
    const float* __restrict__ wih0f, const float* __restrict__ wih0b,
    const float* __restrict__ bih0f, const float* __restrict__ bhh0f,
    const float* __restrict__ bih0b, const float* __restrict__ bhh0b,
    const float* __restrict__ wih1f, const float* __restrict__ wih1b,
    const float* __restrict__ bih1f, const float* __restrict__ bhh1f,
    const float* __restrict__ bih1b, const float* __restrict__ bhh1b)
{
    int i = blockIdx.x*256 + threadIdx.x;
    if (i < 800*KPD2_0) {
        int n = i / KPD2_0, kk = i % KPD2_0;
        int k0 = 2*kk, k1 = 2*kk + 1;
        float v0 = (k0 < EE) ? ((n < 400) ? wih0f[n*EE + k0] : wih0b[(n-400)*EE + k0]) : 0.f;
        float v1 = (k1 < EE) ? ((n < 400) ? wih0f[n*EE + k1] : wih0b[(n-400)*EE + k1]) : 0.f;
        unsigned short h0, l0, h1, l1;
        bfsplit(v0, h0, l0); bfsplit(v1, h1, l1);
        g_Bh0[i] = (uint32_t)h0 | ((uint32_t)h1 << 16);
        g_Bl0[i] = (uint32_t)l0 | ((uint32_t)l1 << 16);
    } else if (i < 800*KPD2_0 + 800*KPD2_1) {
        int j = i - 800*KPD2_0;
        int n = j / KPD2_1, kk = j % KPD2_1;
        int k0 = 2*kk, k1 = 2*kk + 1;
        float v0 = (k0 < 200) ? ((n < 400) ? wih1f[n*200 + k0] : wih1b[(n-400)*200 + k0]) : 0.f;
        float v1 = (k1 < 200) ? ((n < 400) ? wih1f[n*200 + k1] : wih1b[(n-400)*200 + k1]) : 0.f;
        unsigned short h0, l0, h1, l1;
        bfsplit(v0, h0, l0); bfsplit(v1, h1, l1);
        g_Bh1[j] = (uint32_t)h0 | ((uint32_t)h1 << 16);
        g_Bl1[j] = (uint32_t)l0 | ((uint32_t)l1 << 16);
    } else if (i < 800*KPD2_0 + 800*KPD2_1 + 800) {
        int n = i - (800*KPD2_0 + 800*KPD2_1);
        g_b0[n] = (n < 400) ? (bih0f[n] + bhh0f[n]) : (bih0b[n-400] + bhh0b[n-400]);
    } else if (i < 800*KPD2_0 + 800*KPD2_1 + 1600) {
        int n = i - (800*KPD2_0 + 800*KPD2_1 + 800);
        g_b1[n] = (n < 400) ? (bih1f[n] + bhh1f[n]) : (bih1b[n-400] + bhh1b[n-400]);
    }
}

// ---- whh pack (R8 layout: plain gate rows) -------------------------------------
__global__ void prep_whh(const float* __restrict__ whhf, const float* __restrict__ whhb,
                         uint32_t* __restrict__ Wh, uint32_t* __restrict__ Wl)
{
    int i = blockIdx.x*256 + threadIdx.x;
    if (i >= 2*400*56) return;
    int d = i / (400*56);
    int rem = i - d*(400*56);
    int g = rem / 56, w = rem % 56;
    const float* W = d ? whhb : whhf;
    int k0 = 2*w, k1 = 2*w + 1;
    float v0 = (k0 < 100) ? W[g*100 + k0] : 0.f;
    float v1 = (k1 < 100) ? W[g*100 + k1] : 0.f;
    unsigned short h0, l0, h1, l1;
    bfsplit(v0, h0, l0); bfsplit(v1, h1, l1);
    Wh[i] = (uint32_t)h0 | ((uint32_t)h1 << 16);
    Wl[i] = (uint32_t)l0 | ((uint32_t)l1 << 16);
}

// ---- A split pass --------------------------------------------------------------
__global__ void split_a(const float* __restrict__ A, uint32_t* __restrict__ Ah,
                        uint32_t* __restrict__ Al, int M, int K, int kpd2)
{
    size_t i = (size_t)blockIdx.x*256 + threadIdx.x;
    if (i >= (size_t)M*kpd2) return;
    int kk = (int)(i % kpd2);
    size_t r = i / kpd2;
    int k0 = 2*kk, k1 = 2*kk + 1;
    float v0 = (k0 < K) ? A[r*K + k0] : 0.f;
    float v1 = (k1 < K) ? A[r*K + k1] : 0.f;
    unsigned short h0, l0, h1, l1;
    bfsplit(v0, h0, l0); bfsplit(v1, h1, l1);
    Ah[i] = (uint32_t)h0 | ((uint32_t)h1 << 16);
    Al[i] = (uint32_t)l0 | ((uint32_t)l1 << 16);
}

// ---- HMMA bf16 3-term GEMM: block 64x160, 2 blocks/SM --------------------------
#define AS_OFF(bf,s,r,q) ((((bf)*2 + (s))*64 + (r))*20 + (q))
#define BS_OFF(bf,s,r,q) (5120 + (((bf)*2 + (s))*160 + (r))*20 + (q))
#define GSM_BYTES (17920*4)

__global__ void __launch_bounds__(256, 2) mma_gemm(
    const uint32_t* __restrict__ Ah, const uint32_t* __restrict__ Al,
    const uint32_t* __restrict__ Bh, const uint32_t* __restrict__ Bl,
    const float* __restrict__ bias, float* __restrict__ C,
    int M, int kpd2, int nc)
{
    extern __shared__ uint32_t s32[];
    const uint32_t sb = smem_u32(s32);
    const int tid = threadIdx.x;
    const int bm  = blockIdx.y * 64;
    const int bn0 = blockIdx.x * 160;
    const int warp = tid >> 5, lane = tid & 31;
    const int wm = (warp & 1) * 32;
    const int wn = (warp >> 1) * 40;
    const int g = lane >> 2, tig = lane & 3;

    float acc[2][5][4];
    #pragma unroll
    for (int mf = 0; mf < 2; mf++)
        #pragma unroll
        for (int nf = 0; nf < 5; nf++)
            #pragma unroll
            for (int c = 0; c < 4; c++) acc[mf][nf][c] = 0.f;

    auto stageA = [&](int ci, int bf) {
        #pragma unroll
        for (int j = 0; j < 2; j++) {
            int idx = tid + 256*j;
            int s = idx >> 8;
            int r = (idx >> 2) & 63;
            int q = idx & 3;
            const uint32_t* base = s ? Al : Ah;
            int row = bm + r;
            const uint32_t* src = (row < M) ? (base + (size_t)row*kpd2 + ci*16 + q*4) : base;
            cpa16z(sb + 4*AS_OFF(bf, s, r, q*4), src, (row < M) ? 16u : 0u);
        }
    };
    auto stageB = [&](int ci, int bf) {
        #pragma unroll
        for (int j = 0; j < 5; j++) {
            int idx = tid + 256*j;
            int s = idx / 640;
            int rem = idx - s*640;
            int r = rem >> 2;
            int q = rem & 3;
            const uint32_t* base = s ? Bl : Bh;
            cpa16(sb + 4*BS_OFF(bf, s, r, q*4), base + (size_t)(bn0 + r)*kpd2 + ci*16 + q*4);
        }
    };

    stageA(0, 0); stageB(0, 0); CP_COMMIT();
    stageA(1, 1); stageB(1, 1); CP_COMMIT();

    for (int ci = 0; ci < nc; ci++) {
        const int bf = ci & 1;
        if (ci + 1 < nc) { CP_WAIT(1); } else { CP_WAIT(0); }
        __syncthreads();

        #pragma unroll
        for (int ks = 0; ks < 2; ks++) {
            const int kb = 8*ks;
            uint32_t aH[2][4], aL[2][4], bH[5][2], bL[5][2];
            #pragma unroll
            for (int mf = 0; mf < 2; mf++) {
                int r0 = wm + mf*16 + g;
                aH[mf][0] = s32[AS_OFF(bf,0,r0,   kb+tig)];
                aH[mf][1] = s32[AS_OFF(bf,0,r0+8, kb+tig)];
                aH[mf][2] = s32[AS_OFF(bf,0,r0,   kb+4+tig)];
                aH[mf][3] = s32[AS_OFF(bf,0,r0+8, kb+4+tig)];
                aL[mf][0] = s32[AS_OFF(bf,1,r0,   kb+tig)];
                aL[mf][1] = s32[AS_OFF(bf,1,r0+8, kb+tig)];
                aL[mf][2] = s32[AS_OFF(bf,1,r0,   kb+4+tig)];
                aL[mf][3] = s32[AS_OFF(bf,1,r0+8, kb+4+tig)];
            }
            #pragma unroll
            for (int nf = 0; nf < 5; nf++) {
                int n = wn + nf*8 + g;
                bH[nf][0] = s32[BS_OFF(bf,0,n, kb+tig)];
                bH[nf][1] = s32[BS_OFF(bf,0,n, kb+4+tig)];
                bL[nf][0] = s32[BS_OFF(bf,1,n, kb+tig)];
                bL[nf][1] = s32[BS_OFF(bf,1,n, kb+4+tig)];
            }
            #pragma unroll
            for (int mf = 0; mf < 2; mf++)
                #pragma unroll
                for (int nf = 0; nf < 5; nf++) {
                    mma16816(acc[mf][nf], aH[mf], bH[nf]);
                    mma16816(acc[mf][nf], aH[mf], bL[nf]);
                    mma16816(acc[mf][nf], aL[mf], bH[nf]);
                }
        }

        if (ci + 2 < nc) {
            __syncthreads();
            stageA(ci + 2, bf); stageB(ci + 2, bf); CP_COMMIT();
        }
    }

    #pragma unroll
    for (int mf = 0; mf < 2; mf++) {
        int r0 = bm + wm + mf*16 + g;
        #pragma unroll
        for (int nf = 0; nf < 5; nf++) {
            int col = bn0 + wn + nf*8 + 2*tig;
            float b0v = bias[col], b1v = bias[col + 1];
            if (r0 < M) {
                float2 o = make_float2(acc[mf][nf][0] + b0v, acc[mf][nf][1] + b1v);
                *(float2*)&C[(size_t)r0*800 + col] = o;
            }
            if (r0 + 8 < M) {
                float2 o = make_float2(acc[mf][nf][2] + b0v, acc[mf][nf][3] + b1v);
                *(float2*)&C[(size_t)(r0 + 8)*800 + col] = o;
            }
        }
    }
}

// ---- HMMA-based persistent BiLSTM recurrence (R8 version — best measured) ------
__global__ void __launch_bounds__(800, 1) lstm_layer(
    const float* __restrict__ xsrc, const int* __restrict__ sentence,
    const uint32_t* __restrict__ Wpkh, const uint32_t* __restrict__ Wpkl,
    float* __restrict__ hout, int mode)
{
    __shared__ uint32_t Hh[448];
    __shared__ uint32_t Hl[448];
    __shared__ float ps[3200];
    __shared__ int tok_s[8];
    const int tid  = threadIdx.x;
    const int warp = tid >> 5, lane = tid & 31;
    const int q = lane & 3, n = lane >> 2;
    const int dir = blockIdx.x >> 6;
    const int b0  = (blockIdx.x & 63) * 8;
    const int xofs = dir * 400;

    const uint32_t* Wbh = Wpkh + dir*22400;
    const uint32_t* Wbl = Wpkl + dir*22400;
    const int g0 = warp*16 + n;
    uint32_t Ahr[26], Alr[26];
    #pragma unroll
    for (int ks = 0; ks < 6; ks++) {
        Ahr[ks*4+0] = Wbh[ g0    *56 + ks*8 + q];
        Ahr[ks*4+1] = Wbh[(g0+8)*56 + ks*8 + q];
        Ahr[ks*4+2] = Wbh[ g0    *56 + ks*8 + 4 + q];
        Ahr[ks*4+3] = Wbh[(g0+8)*56 + ks*8 + 4 + q];
        Alr[ks*4+0] = Wbl[ g0    *56 + ks*8 + q];
        Alr[ks*4+1] = Wbl[(g0+8)*56 + ks*8 + q];
        Alr[ks*4+2] = Wbl[ g0    *56 + ks*8 + 4 + q];
        Alr[ks*4+3] = Wbl[(g0+8)*56 + ks*8 + 4 + q];
    }
    Ahr[24] = Wbh[g0*56 + 48 + q];  Ahr[25] = Wbh[(g0+8)*56 + 48 + q];
    Alr[24] = Wbl[g0*56 + 48 + q];  Alr[25] = Wbl[(g0+8)*56 + 48 + q];

    for (int i = tid; i < 448; i += 800) { Hh[i] = 0; Hl[i] = 0; }

    const int hh2 = tid >> 3, ab = tid & 7;
    const int h0 = 2*hh2;
    const int aks = h0 >> 4, akk = h0 & 15;
    const int aw = ((aks*4 + ((akk & 7) >> 1))*8 + ab)*2 + (akk >> 3);
    float c0 = 0.f, c1 = 0.f;

    for (int step = 0; step < TT; step++) {
        const int t = dir ? (TT - 1 - step) : step;
        if (mode == 0 && tid < 8) tok_s[tid] = sentence[t*BB + b0 + tid];
        __syncthreads();

        float2 xv0, xv1, xv2, xv3;
        if (tid < 400) {
            const float* xr;
            if (mode == 0) xr = xsrc + (size_t)tok_s[ab]*800 + xofs + h0;
            else           xr = xsrc + ((size_t)t*BB + b0 + ab)*800 + xofs + h0;
            xv0 = *(const float2*)xr;
            xv1 = *(const float2*)(xr + 100);
            xv2 = *(const float2*)(xr + 200);
            xv3 = *(const float2*)(xr + 300);
        }

        float d4[4] = {0.f, 0.f, 0.f, 0.f};
        #pragma unroll
        for (int ks = 0; ks < 6; ks++) {
            uint2 bh = *(const uint2*)&Hh[(ks*32 + q*8 + n)*2];
            uint2 bl = *(const uint2*)&Hl[(ks*32 + q*8 + n)*2];
            mma16816v(d4, &Ahr[ks*4], bh.x, bh.y);
            mma16816v(d4, &Alr[ks*4], bh.x, bh.y);
            mma16816v(d4, &Ahr[ks*4], bl.x, bl.y);
        }
        {
            uint32_t bh6 = Hh[(192 + q*8 + n)*2];
            uint32_t bl6 = Hl[(192 + q*8 + n)*2];
            mma1688(d4, Ahr[24], Ahr[25], bh6);
            mma1688(d4, Alr[24], Alr[25], bh6);
            mma1688(d4, Ahr[24], Ahr[25], bl6);
        }
        {
            float* pp = ps + g0*8 + q*2;
            *(float2*)pp        = make_float2(d4[0], d4[1]);
            *(float2*)(pp + 64) = make_float2(d4[2], d4[3]);
        }
        __syncthreads();

        if (tid < 400) {
            float gi0 = ps[ h0      *8 + ab] + xv0.x, gi1 = ps[(h0+1)  *8 + ab] + xv0.y;
            float gf0 = ps[(h0+100)*8 + ab] + xv1.x, gf1 = ps[(h0+101)*8 + ab] + xv1.y;
            float gg0 = ps[(h0+200)*8 + ab] + xv2.x, gg1 = ps[(h0+201)*8 + ab] + xv2.y;
            float go0 = ps[(h0+300)*8 + ab] + xv3.x, go1 = ps[(h0+301)*8 + ab] + xv3.y;
            float iv0 = sigf(gi0), fv0 = sigf(gf0), gv0 = tanhfast(gg0), ov0 = sigf(go0);
            float iv1 = sigf(gi1), fv1 = sigf(gf1), gv1 = tanhfast(gg1), ov1 = sigf(go1);
            c0 = fv0*c0 + iv0*gv0;
            c1 = fv1*c1 + iv1*gv1;
            float hv0 = ov0 * tanhfast(c0);
            float hv1 = ov1 * tanhfast(c1);
            *(float2*)&hout[((size_t)t*BB + b0 + ab)*200 + dir*100 + h0] = make_float2(hv0, hv1);
            unsigned short s0h, s0l, s1h, s1l;
            bfsplit(hv0, s0h, s0l);
            bfsplit(hv1, s1h, s1l);
            Hh[aw] = (uint32_t)s0h | ((uint32_t)s1h << 16);
            Hl[aw] = (uint32_t)s0l | ((uint32_t)s1l << 16);
        }
    }
}

// ---- emissions -----------------------------------------------------------------
__global__ void __launch_bounds__(256) em_kernel(
    const float* __restrict__ h2, const float* __restrict__ wl,
    const float* __restrict__ bl, float* __restrict__ em)
{
    __shared__ float wls[1600];
    __shared__ float bls[8];
    int tid = threadIdx.x;
    for (int i = tid; i < 1600; i += 256) wls[i] = wl[i];
    if (tid < 8) bls[tid] = bl[tid];
    __syncthreads();
    int warp = tid >> 5, lane = tid & 31;
    size_t row = (size_t)blockIdx.x*8 + warp;
    float acc[8] = {0.f,0.f,0.f,0.f,0.f,0.f,0.f,0.f};
    const float* hr = h2 + row*200;
    #pragma unroll
    for (int i = 0; i < 7; i++) {
        int k = lane + i*32;
        if (k < 200) {
            float x = hr[k];
            #pragma unroll
            for (int gg = 0; gg < 8; gg++) acc[gg] += x * wls[gg*200 + k];
        }
    }
    #pragma unroll
    for (int gg = 0; gg < 8; gg++) {
        float v = acc[gg];
        #pragma unroll
        for (int o = 16; o > 0; o >>= 1) v += __shfl_xor_sync(0xffffffffu, v, o);
        if (lane == 0) em[row*8 + gg] = v + bls[gg];
    }
}

// ---- CRF forward ---------------------------------------------------------------
__global__ void __launch_bounds__(256) crf_fwd(
    const float* __restrict__ em, const int* __restrict__ tags,
    const float* __restrict__ start_t, const float* __restrict__ end_t,
    const float* __restrict__ trans, float* __restrict__ pl)
{
    int tid = blockIdx.x*256 + threadIdx.x;
    int b = tid >> 3, k = tid & 7;
    float trcol[8];
    #pragma unroll
    for (int kk = 0; kk < 8; kk++) trcol[kk] = trans[kk*8 + k];

    float score = start_t[k] + em[(size_t)b*8 + k];

    float nump = 0.f;
    for (int t = 1 + k; t < TT; t += 8) {
        int tp = tags[(t-1)*BB + b];
        int tc = tags[t*BB + b];
        nump += trans[tp*8 + tc] + em[((size_t)t*BB + b)*8 + tc];
    }
    if (k == 0) {
        int t0 = tags[b];
        nump += start_t[t0] + em[(size_t)b*8 + t0] + end_t[tags[(TT-1)*BB + b]];
    }

    for (int t = 1; t < TT; t++) {
        float e = em[((size_t)t*BB + b)*8 + k];
        float v[8];
        float m = -3.4e38f;
        #pragma unroll
        for (int kk = 0; kk < 8; kk++) {
            float s = __shfl_sync(0xffffffffu, score, kk, 8);
            v[kk] = s + trcol[kk];
            m = fmaxf(m, v[kk]);
        }
        float ss = 0.f;
        #pragma unroll
        for (int kk = 0; kk < 8; kk++) ss += expf(v[kk] - m);
        score = m + logf(ss) + e;
    }

    float v = score + end_t[k];
    float m = v;
    #pragma unroll
    for (int kk = 0; kk < 8; kk++) m = fmaxf(m, __shfl_sync(0xffffffffu, v, kk, 8));
    float ex = expf(v - m);
    float ssum = 0.f;
    #pragma unroll
    for (int kk = 0; kk < 8; kk++) ssum += __shfl_sync(0xffffffffu, ex, kk, 8);
    float denom = m + logf(ssum);

    float nsum = 0.f;
    #pragma unroll
    for (int kk = 0; kk < 8; kk++) nsum += __shfl_sync(0xffffffffu, nump, kk, 8);
    if (k == 0) pl[b] = nsum - denom;
}

// ---- Viterbi -------------------------------------------------------------------
__global__ void __launch_bounds__(256) viterbi_k(
    const float* __restrict__ em, const float* __restrict__ start_t,
    const float* __restrict__ end_t, const float* __restrict__ trans,
    unsigned char* __restrict__ hist, float* __restrict__ dec)
{
    int tid = blockIdx.x*256 + threadIdx.x;
    int b = tid >> 3, k = tid & 7;
    float trcol[8];
    #pragma unroll
    for (int kk = 0; kk < 8; kk++) trcol[kk] = trans[kk*8 + k];

    float score = start_t[k] + em[(size_t)b*8 + k];
    for (int t = 1; t < TT; t++) {
        float e = em[((size_t)t*BB + b)*8 + k];
        float best = -3.4e38f;
        int arg = 0;
        #pragma unroll
        for (int kk = 0; kk < 8; kk++) {
            float s = __shfl_sync(0xffffffffu, score, kk, 8) + trcol[kk];
            if (s > best) { best = s; arg = kk; }
        }
        hist[((size_t)(t-1)*BB + b)*8 + k] = (unsigned char)arg;
        score = best + e;
    }
    float v = score + end_t[k];
    float best = -3.4e38f;
    int arg = 0;
    #pragma unroll
    for (int kk = 0; kk < 8; kk++) {
        float s = __shfl_sync(0xffffffffu, v, kk, 8);
        if (s > best) { best = s; arg = kk; }
    }
    __syncwarp();
    if (k == 0) {
        int nxt = arg;
        dec[(size_t)(TT-1)*BB + b] = (float)nxt;
        for (int i = TT - 2; i >= 0; i--) {
            nxt = hist[((size_t)i*BB + b)*8 + nxt];
            dec[(size_t)i*BB + b] = (float)nxt;
        }
    }
}

// ---- deterministic loss reduction ----------------------------------------------
__global__ void loss_reduce(const float* __restrict__ pl, float* __restrict__ out)
{
    __shared__ float s[512];
    int tid = threadIdx.x;
    s[tid] = pl[tid];
    __syncthreads();
    for (int ofs = 256; ofs > 0; ofs >>= 1) {
        if (tid < ofs) s[tid] += s[tid + ofs];
        __syncthreads();
    }
    if (tid == 0) out[0] = s[0];
}

// ---- host launch ---------------------------------------------------------------
extern "C" void kernel_launch(void* const* d_in, const int* in_sizes, int n_in,
                              void* d_out, int out_size)
{
    const int*   sentence = (const int*)d_in[0];
    const int*   tags     = (const int*)d_in[1];
    const float* emb      = (const float*)d_in[3];
    const float* wih0f = (const float*)d_in[4];
    const float* whh0f = (const float*)d_in[5];
    const float* bih0f = (const float*)d_in[6];
    const float* bhh0f = (const float*)d_in[7];
    const float* wih0b = (const float*)d_in[8];
    const float* whh0b = (const float*)d_in[9];
    const float* bih0b = (const float*)d_in[10];
    const float* bhh0b = (const float*)d_in[11];
    const float* wih1f = (const float*)d_in[12];
    const float* whh1f = (const float*)d_in[13];
    const float* bih1f = (const float*)d_in[14];
    const float* bhh1f = (const float*)d_in[15];
    const float* wih1b = (const float*)d_in[16];
    const float* whh1b = (const float*)d_in[17];
    const float* bih1b = (const float*)d_in[18];
    const float* bhh1b = (const float*)d_in[19];
    const float* wl      = (const float*)d_in[20];
    const float* bl      = (const float*)d_in[21];
    const float* start_t = (const float*)d_in[22];
    const float* end_t   = (const float*)d_in[23];
    const float* trans   = (const float*)d_in[24];
    float* out = (float*)d_out;

    void* p;
    cudaGetSymbolAddress(&p, g_Bh0);     uint32_t* pBh0 = (uint32_t*)p;
    cudaGetSymbolAddress(&p, g_Bl0);     uint32_t* pBl0 = (uint32_t*)p;
    cudaGetSymbolAddress(&p, g_Bh1);     uint32_t* pBh1 = (uint32_t*)p;
    cudaGetSymbolAddress(&p, g_Bl1);     uint32_t* pBl1 = (uint32_t*)p;
    cudaGetSymbolAddress(&p, g_b0);      float* pB0   = (float*)p;
    cudaGetSymbolAddress(&p, g_b1);      float* pB1   = (float*)p;
    cudaGetSymbolAddress(&p, g_Wpk_h);   uint32_t* pWph = (uint32_t*)p;
    cudaGetSymbolAddress(&p, g_Wpk_l);   uint32_t* pWpl = (uint32_t*)p;
    cudaGetSymbolAddress(&p, g_A0h);     uint32_t* pA0h = (uint32_t*)p;
    cudaGetSymbolAddress(&p, g_A0l);     uint32_t* pA0l = (uint32_t*)p;
    cudaGetSymbolAddress(&p, g_A1h);     uint32_t* pA1h = (uint32_t*)p;
    cudaGetSymbolAddress(&p, g_A1l);     uint32_t* pA1l = (uint32_t*)p;
    cudaGetSymbolAddress(&p, g_projemb); float* pProj = (float*)p;
    cudaGetSymbolAddress(&p, g_h1);      float* pH1   = (float*)p;
    cudaGetSymbolAddress(&p, g_xp1);     float* pXp1  = (float*)p;
    cudaGetSymbolAddress(&p, g_h2);      float* pH2   = (float*)p;
    cudaGetSymbolAddress(&p, g_em);      float* pEm   = (float*)p;
    cudaGetSymbolAddress(&p, g_hist);    unsigned char* pHist = (unsigned char*)p;
    cudaGetSymbolAddress(&p, g_pl);      float* pPl   = (float*)p;

    cudaFuncSetAttribute(mma_gemm, cudaFuncAttributeMaxDynamicSharedMemorySize, GSM_BYTES);

    prep_kernel<<<(800*KPD2_0 + 800*KPD2_1 + 1600 + 255)/256, 256>>>(
        wih0f, wih0b, bih0f, bhh0f, bih0b, bhh0b,
        wih1f, wih1b, bih1f, bhh1f, bih1b, bhh1b);

    prep_whh<<<(2*400*56 + 255)/256, 256>>>(whh0f, whh0b, pWph, pWpl);

    {
        size_t tot = (size_t)VV*KPD2_0;
        split_a<<<(unsigned)((tot + 255)/256), 256>>>(emb, pA0h, pA0l, VV, EE, KPD2_0);
    }

    mma_gemm<<<dim3(5, (VV + 63)/64), 256, GSM_BYTES>>>(
        pA0h, pA0l, pBh0, pBl0, pB0, pProj, VV, KPD2_0, KPAD0/32);

    lstm_layer<<<128, 800>>>(pProj, sentence, pWph, pWpl, pH1, 0);

    prep_whh<<<(2*400*56 + 255)/256, 256>>>(whh1f, whh1b, pWph, pWpl);

    {
        size_t tot = (size_t)NN*KPD2_1;
        split_a<<<(unsigned)((tot + 255)/256), 256>>>(pH1, pA1h, pA1l, NN, 200, KPD2_1);
    }

    mma_gemm<<<dim3(5, NN/64), 256, GSM_BYTES>>>(
        pA1h, pA1l, pBh1, pBl1, pB1, pXp1, NN, KPD2_1, KPAD1/32);

    lstm_layer<<<128, 800>>>(pXp1, (const int*)0, pWph, pWpl, pH2, 1);

    em_kernel<<<NN/8, 256>>>(pH2, wl, bl, pEm);

    crf_fwd<<<BB*KCRF/256, 256>>>(pEm, tags, start_t, end_t, trans, pPl);

    viterbi_k<<<BB*KCRF/256, 256>>>(pEm, start_t, end_t, trans, pHist, out + 1);

    loss_reduce<<<1, 512>>>(pPl, out);
}

// round 14
// speedup vs baseline: 1.0409x; 1.0209x over previous
#include <cuda_runtime.h>
#include <cuda_bf16.h>
#include <math.h>
#include <stdint.h>

#define TT 256
#define BB 512
#define VV 50000
#define EE 300
#define HHH 100
#define KCRF 8
#define NN (TT*BB)

#define KPAD0 320
#define KPD2_0 160
#define KPAD1 224
#define KPD2_1 112

typedef unsigned long long ull;

// ---- helpers -------------------------------------------------------------------
__device__ __forceinline__ float sigf(float x) { return __frcp_rn(1.f + __expf(-x)); }
__device__ __forceinline__ float tanhfast(float x) { return __fmaf_rn(2.f, sigf(2.f*x), -1.f); }

__device__ __forceinline__ unsigned short bfbits(float a) {
    __nv_bfloat16 h = __float2bfloat16_rn(a);
    return *reinterpret_cast<unsigned short*>(&h);
}
__device__ __forceinline__ float bf2f(unsigned short u) {
    __nv_bfloat16 h = *reinterpret_cast<__nv_bfloat16*>(&u);
    return __bfloat162float(h);
}
__device__ __forceinline__ void bfsplit(float v, unsigned short &hi, unsigned short &lo) {
    hi = bfbits(v);
    lo = bfbits(v - bf2f(hi));
}

__device__ __forceinline__ uint32_t smem_u32(const void* p) {
    uint32_t a;
    asm("{ .reg .u64 t; cvta.to.shared.u64 t, %1; cvt.u32.u64 %0, t; }" : "=r"(a) : "l"(p));
    return a;
}
__device__ __forceinline__ void cpa16(uint32_t dst, const void* src) {
    asm volatile("cp.async.cg.shared.global [%0], [%1], 16;" :: "r"(dst), "l"(src));
}
__device__ __forceinline__ void cpa16z(uint32_t dst, const void* src, uint32_t ssz) {
    asm volatile("cp.async.cg.shared.global [%0], [%1], 16, %2;" :: "r"(dst), "l"(src), "r"(ssz));
}
#define CP_COMMIT() asm volatile("cp.async.commit_group;" ::: "memory")
#define CP_WAIT(n)  asm volatile("cp.async.wait_group %0;" :: "n"(n) : "memory")

// ---- mma.sync ------------------------------------------------------------------
__device__ __forceinline__ void mma16816(float d[4], const uint32_t a[4], const uint32_t b[2]) {
    asm volatile("mma.sync.aligned.m16n8k16.row.col.f32.bf16.bf16.f32 "
        "{%0,%1,%2,%3}, {%4,%5,%6,%7}, {%8,%9}, {%0,%1,%2,%3};"
        : "+f"(d[0]), "+f"(d[1]), "+f"(d[2]), "+f"(d[3])
        : "r"(a[0]), "r"(a[1]), "r"(a[2]), "r"(a[3]), "r"(b[0]), "r"(b[1]));
}
__device__ __forceinline__ void mma16816v(float d[4], const uint32_t a[4], uint32_t b0, uint32_t b1) {
    asm volatile("mma.sync.aligned.m16n8k16.row.col.f32.bf16.bf16.f32 "
        "{%0,%1,%2,%3}, {%4,%5,%6,%7}, {%8,%9}, {%0,%1,%2,%3};"
        : "+f"(d[0]), "+f"(d[1]), "+f"(d[2]), "+f"(d[3])
        : "r"(a[0]), "r"(a[1]), "r"(a[2]), "r"(a[3]), "r"(b0), "r"(b1));
}
__device__ __forceinline__ void mma1688(float d[4], uint32_t a0, uint32_t a1, uint32_t b0) {
    asm volatile("mma.sync.aligned.m16n8k8.row.col.f32.bf16.bf16.f32 "
        "{%0,%1,%2,%3}, {%4,%5}, {%6}, {%0,%1,%2,%3};"
        : "+f"(d[0]), "+f"(d[1]), "+f"(d[2]), "+f"(d[3])
        : "r"(a0), "r"(a1), "r"(b0));
}

// ---- scratch -------------------------------------------------------------------
__device__ uint32_t g_Bh0[800*KPD2_0];
__device__ uint32_t g_Bl0[800*KPD2_0];
__device__ uint32_t g_Bh1[800*KPD2_1];
__device__ uint32_t g_Bl1[800*KPD2_1];
__device__ float    g_b0[800];
__device__ float    g_b1[800];
__device__ uint32_t g_Wpk_h[4*400*56];   // [layer][dir][gate][k2]
__device__ uint32_t g_Wpk_l[4*400*56];
__device__ uint32_t g_A0h[(size_t)VV*KPD2_0];
__device__ uint32_t g_A0l[(size_t)VV*KPD2_0];
__device__ uint32_t g_A1h[(size_t)NN*KPD2_1];
__device__ uint32_t g_A1l[(size_t)NN*KPD2_1];
__device__ float    g_projemb[(size_t)VV*800];
__device__ float    g_xp1[(size_t)NN*800];
__device__ float    g_h2[(size_t)NN*200];
__device__ float    g_em[(size_t)NN*KCRF];
__device__ unsigned char g_hist[(size_t)(TT-1)*BB*KCRF];
__device__ float    g_pl[BB];

// ---- weight prep (input-proj weights for GEMM) ---------------------------------
__global__ void prep_kernel(
    const float* __restrict__ wih0f, const float* __restrict__ wih0b,
    const float* __restrict__ bih0f, const float* __restrict__ bhh0f,
    const float* __restrict__ bih0b, const float* __restrict__ bhh0b,
    const float* __restrict__ wih1f, const float* __restrict__ wih1b,
    const float* __restrict__ bih1f, const float* __restrict__ bhh1f,
    const float* __restrict__ bih1b, const float* __restrict__ bhh1b)
{
    int i = blockIdx.x*256 + threadIdx.x;
    if (i < 800*KPD2_0) {
        int n = i / KPD2_0, kk = i % KPD2_0;
        int k0 = 2*kk, k1 = 2*kk + 1;
        float v0 = (k0 < EE) ? ((n < 400) ? wih0f[n*EE + k0] : wih0b[(n-400)*EE + k0]) : 0.f;
        float v1 = (k1 < EE) ? ((n < 400) ? wih0f[n*EE + k1] : wih0b[(n-400)*EE + k1]) : 0.f;
        unsigned short h0, l0, h1, l1;
        bfsplit(v0, h0, l0); bfsplit(v1, h1, l1);
        g_Bh0[i] = (uint32_t)h0 | ((uint32_t)h1 << 16);
        g_Bl0[i] = (uint32_t)l0 | ((uint32_t)l1 << 16);
    } else if (i < 800*KPD2_0 + 800*KPD2_1) {
        int j = i - 800*KPD2_0;
        int n = j / KPD2_1, kk = j % KPD2_1;
        int k0 = 2*kk, k1 = 2*kk + 1;
        float v0 = (k0 < 200) ? ((n < 400) ? wih1f[n*200 + k0] : wih1b[(n-400)*200 + k0]) : 0.f;
        float v1 = (k1 < 200) ? ((n < 400) ? wih1f[n*200 + k1] : wih1b[(n-400)*200 + k1]) : 0.f;
        unsigned short h0, l0, h1, l1;
        bfsplit(v0, h0, l0); bfsplit(v1, h1, l1);
        g_Bh1[j] = (uint32_t)h0 | ((uint32_t)h1 << 16);
        g_Bl1[j] = (uint32_t)l0 | ((uint32_t)l1 << 16);
    } else if (i < 800*KPD2_0 + 800*KPD2_1 + 800) {
        int n = i - (800*KPD2_0 + 800*KPD2_1);
        g_b0[n] = (n < 400) ? (bih0f[n] + bhh0f[n]) : (bih0b[n-400] + bhh0b[n-400]);
    } else if (i < 800*KPD2_0 + 800*KPD2_1 + 1600) {
        int n = i - (800*KPD2_0 + 800*KPD2_1 + 800);
        g_b1[n] = (n < 400) ? (bih1f[n] + bhh1f[n]) : (bih1b[n-400] + bhh1b[n-400]);
    }
}

// ---- whh pack for BOTH layers in one pass --------------------------------------
__global__ void prep_whh2(const float* __restrict__ whh0f, const float* __restrict__ whh0b,
                          const float* __restrict__ whh1f, const float* __restrict__ whh1b,
                          uint32_t* __restrict__ Wh, uint32_t* __restrict__ Wl)
{
    int i = blockIdx.x*256 + threadIdx.x;
    if (i >= 4*400*56) return;
    int ld = i / (2*400*56);                 // layer
    int rem0 = i - ld*(2*400*56);
    int d = rem0 / (400*56);                  // dir
    int rem = rem0 - d*(400*56);
    int g = rem / 56, w = rem % 56;
    const float* W = ld ? (d ? whh1b : whh1f) : (d ? whh0b : whh0f);
    int k0 = 2*w, k1 = 2*w + 1;
    float v0 = (k0 < 100) ? W[g*100 + k0] : 0.f;
    float v1 = (k1 < 100) ? W[g*100 + k1] : 0.f;
    unsigned short h0, l0, h1, l1;
    bfsplit(v0, h0, l0); bfsplit(v1, h1, l1);
    Wh[i] = (uint32_t)h0 | ((uint32_t)h1 << 16);
    Wl[i] = (uint32_t)l0 | ((uint32_t)l1 << 16);
}

// ---- A split pass (emb only) ---------------------------------------------------
__global__ void split_a(const float* __restrict__ A, uint32_t* __restrict__ Ah,
                        uint32_t* __restrict__ Al, int M, int K, int kpd2)
{
    size_t i = (size_t)blockIdx.x*256 + threadIdx.x;
    if (i >= (size_t)M*kpd2) return;
    int kk = (int)(i % kpd2);
    size_t r = i / kpd2;
    int k0 = 2*kk, k1 = 2*kk + 1;
    float v0 = (k0 < K) ? A[r*K + k0] : 0.f;
    float v1 = (k1 < K) ? A[r*K + k1] : 0.f;
    unsigned short h0, l0, h1, l1;
    bfsplit(v0, h0, l0); bfsplit(v1, h1, l1);
    Ah[i] = (uint32_t)h0 | ((uint32_t)h1 << 16);
    Al[i] = (uint32_t)l0 | ((uint32_t)l1 << 16);
}

// ---- zero padding cols 100..111 of the layer-1 A operand (one-time) ------------
__global__ void zero_tail(uint32_t* __restrict__ Ah, uint32_t* __restrict__ Al)
{
    size_t i = (size_t)blockIdx.x*256 + threadIdx.x;
    if (i >= (size_t)NN*12) return;
    size_t row = i / 12;
    int cc = 100 + (int)(i % 12);
    Ah[row*112 + cc] = 0;
    Al[row*112 + cc] = 0;
}

// ---- HMMA bf16 3-term GEMM (R8 128x160 version — measured best) ----------------
#define AS_OFF(bf,s,r,q) ((((bf)*2 + (s))*128 + (r))*20 + (q))
#define BS_OFF(bf,s,r,q) (10240 + (((bf)*2 + (s))*160 + (r))*20 + (q))
#define GSM_BYTES (23040*4)

__global__ void __launch_bounds__(256) mma_gemm(
    const uint32_t* __restrict__ Ah, const uint32_t* __restrict__ Al,
    const uint32_t* __restrict__ Bh, const uint32_t* __restrict__ Bl,
    const float* __restrict__ bias, float* __restrict__ C,
    int M, int kpd2, int nc)
{
    extern __shared__ uint32_t s32[];
    const uint32_t sb = smem_u32(s32);
    const int tid = threadIdx.x;
    const int bm  = blockIdx.y * 128;
    const int bn0 = blockIdx.x * 160;
    const int warp = tid >> 5, lane = tid & 31;
    const int wm = (warp & 1) * 64;
    const int wn = (warp >> 1) * 40;
    const int g = lane >> 2, tig = lane & 3;

    float acc[4][5][4];
    #pragma unroll
    for (int mf = 0; mf < 4; mf++)
        #pragma unroll
        for (int nf = 0; nf < 5; nf++)
            #pragma unroll
            for (int c = 0; c < 4; c++) acc[mf][nf][c] = 0.f;

    auto stageA = [&](int ci, int bf) {
        #pragma unroll
        for (int j = 0; j < 4; j++) {
            int idx = tid + 256*j;
            int s = idx >> 9;
            int r = (idx >> 2) & 127;
            int q = idx & 3;
            const uint32_t* base = s ? Al : Ah;
            int row = bm + r;
            const uint32_t* src = (row < M) ? (base + (size_t)row*kpd2 + ci*16 + q*4) : base;
            cpa16z(sb + 4*AS_OFF(bf, s, r, q*4), src, (row < M) ? 16u : 0u);
        }
    };
    auto stageB = [&](int ci, int bf) {
        #pragma unroll
        for (int j = 0; j < 5; j++) {
            int idx = tid + 256*j;
            int s = idx / 640;
            int rem = idx - s*640;
            int r = rem >> 2;
            int q = rem & 3;
            const uint32_t* base = s ? Bl : Bh;
            cpa16(sb + 4*BS_OFF(bf, s, r, q*4), base + (size_t)(bn0 + r)*kpd2 + ci*16 + q*4);
        }
    };

    stageA(0, 0); stageB(0, 0); CP_COMMIT();
    stageA(1, 1); stageB(1, 1); CP_COMMIT();

    for (int ci = 0; ci < nc; ci++) {
        const int bf = ci & 1;
        if (ci + 1 < nc) { CP_WAIT(1); } else { CP_WAIT(0); }
        __syncthreads();

        #pragma unroll
        for (int ks = 0; ks < 2; ks++) {
            const int kb = 8*ks;
            uint32_t aH[4][4], aL[4][4], bH[5][2], bL[5][2];
            #pragma unroll
            for (int mf = 0; mf < 4; mf++) {
                int r0 = wm + mf*16 + g;
                aH[mf][0] = s32[AS_OFF(bf,0,r0,   kb+tig)];
                aH[mf][1] = s32[AS_OFF(bf,0,r0+8, kb+tig)];
                aH[mf][2] = s32[AS_OFF(bf,0,r0,   kb+4+tig)];
                aH[mf][3] = s32[AS_OFF(bf,0,r0+8, kb+4+tig)];
                aL[mf][0] = s32[AS_OFF(bf,1,r0,   kb+tig)];
                aL[mf][1] = s32[AS_OFF(bf,1,r0+8, kb+tig)];
                aL[mf][2] = s32[AS_OFF(bf,1,r0,   kb+4+tig)];
                aL[mf][3] = s32[AS_OFF(bf,1,r0+8, kb+4+tig)];
            }
            #pragma unroll
            for (int nf = 0; nf < 5; nf++) {
                int n = wn + nf*8 + g;
                bH[nf][0] = s32[BS_OFF(bf,0,n, kb+tig)];
                bH[nf][1] = s32[BS_OFF(bf,0,n, kb+4+tig)];
                bL[nf][0] = s32[BS_OFF(bf,1,n, kb+tig)];
                bL[nf][1] = s32[BS_OFF(bf,1,n, kb+4+tig)];
            }
            #pragma unroll
            for (int mf = 0; mf < 4; mf++)
                #pragma unroll
                for (int nf = 0; nf < 5; nf++) {
                    mma16816(acc[mf][nf], aH[mf], bH[nf]);
                    mma16816(acc[mf][nf], aH[mf], bL[nf]);
                    mma16816(acc[mf][nf], aL[mf], bH[nf]);
                }
        }

        if (ci + 2 < nc) {
            __syncthreads();
            stageA(ci + 2, bf); stageB(ci + 2, bf); CP_COMMIT();
        }
    }

    #pragma unroll
    for (int mf = 0; mf < 4; mf++) {
        int r0 = bm + wm + mf*16 + g;
        #pragma unroll
        for (int nf = 0; nf < 5; nf++) {
            int col = bn0 + wn + nf*8 + 2*tig;
            float b0v = bias[col], b1v = bias[col + 1];
            if (r0 < M) {
                float2 o = make_float2(acc[mf][nf][0] + b0v, acc[mf][nf][1] + b1v);
                *(float2*)&C[(size_t)r0*800 + col] = o;
            }
            if (r0 + 8 < M) {
                float2 o = make_float2(acc[mf][nf][2] + b0v, acc[mf][nf][3] + b1v);
                *(float2*)&C[(size_t)(r0 + 8)*800 + col] = o;
            }
        }
    }
}

// ---- HMMA-based persistent BiLSTM recurrence (R8 structure) --------------------
// mode 0: writes packed bf16 hi/lo A-operand words for the layer-1 GEMM (fused split)
// mode 1: writes fp32 h2 for emissions
__global__ void __launch_bounds__(800, 1) lstm_layer(
    const float* __restrict__ xsrc, const int* __restrict__ sentence,
    const uint32_t* __restrict__ Wpkh, const uint32_t* __restrict__ Wpkl,
    float* __restrict__ hout, uint32_t* __restrict__ Aoh, uint32_t* __restrict__ Aol,
    int mode)
{
    __shared__ uint32_t Hh[448];
    __shared__ uint32_t Hl[448];
    __shared__ float ps[3200];
    __shared__ int tok_s[8];
    const int tid  = threadIdx.x;
    const int warp = tid >> 5, lane = tid & 31;
    const int q = lane & 3, n = lane >> 2;
    const int dir = blockIdx.x >> 6;
    const int b0  = (blockIdx.x & 63) * 8;
    const int xofs = dir * 400;

    const uint32_t* Wbh = Wpkh + dir*22400;
    const uint32_t* Wbl = Wpkl + dir*22400;
    const int g0 = warp*16 + n;
    uint32_t Ahr[26], Alr[26];
    #pragma unroll
    for (int ks = 0; ks < 6; ks++) {
        Ahr[ks*4+0] = Wbh[ g0    *56 + ks*8 + q];
        Ahr[ks*4+1] = Wbh[(g0+8)*56 + ks*8 + q];
        Ahr[ks*4+2] = Wbh[ g0    *56 + ks*8 + 4 + q];
        Ahr[ks*4+3] = Wbh[(g0+8)*56 + ks*8 + 4 + q];
        Alr[ks*4+0] = Wbl[ g0    *56 + ks*8 + q];
        Alr[ks*4+1] = Wbl[(g0+8)*56 + ks*8 + q];
        Alr[ks*4+2] = Wbl[ g0    *56 + ks*8 + 4 + q];
        Alr[ks*4+3] = Wbl[(g0+8)*56 + ks*8 + 4 + q];
    }
    Ahr[24] = Wbh[g0*56 + 48 + q];  Ahr[25] = Wbh[(g0+8)*56 + 48 + q];
    Alr[24] = Wbl[g0*56 + 48 + q];  Alr[25] = Wbl[(g0+8)*56 + 48 + q];

    for (int i = tid; i < 448; i += 800) { Hh[i] = 0; Hl[i] = 0; }

    const int hh2 = tid >> 3, ab = tid & 7;
    const int h0 = 2*hh2;
    const int aks = h0 >> 4, akk = h0 & 15;
    const int aw = ((aks*4 + ((akk & 7) >> 1))*8 + ab)*2 + (akk >> 3);
    float c0 = 0.f, c1 = 0.f;

    for (int step = 0; step < TT; step++) {
        const int t = dir ? (TT - 1 - step) : step;
        if (mode == 0 && tid < 8) tok_s[tid] = sentence[t*BB + b0 + tid];
        __syncthreads();

        float2 xv0, xv1, xv2, xv3;
        if (tid < 400) {
            const float* xr;
            if (mode == 0) xr = xsrc + (size_t)tok_s[ab]*800 + xofs + h0;
            else           xr = xsrc + ((size_t)t*BB + b0 + ab)*800 + xofs + h0;
            xv0 = *(const float2*)xr;
            xv1 = *(const float2*)(xr + 100);
            xv2 = *(const float2*)(xr + 200);
            xv3 = *(const float2*)(xr + 300);
        }

        float d4[4] = {0.f, 0.f, 0.f, 0.f};
        #pragma unroll
        for (int ks = 0; ks < 6; ks++) {
            uint2 bh = *(const uint2*)&Hh[(ks*32 + q*8 + n)*2];
            uint2 bl = *(const uint2*)&Hl[(ks*32 + q*8 + n)*2];
            mma16816v(d4, &Ahr[ks*4], bh.x, bh.y);
            mma16816v(d4, &Alr[ks*4], bh.x, bh.y);
            mma16816v(d4, &Ahr[ks*4], bl.x, bl.y);
        }
        {
            uint32_t bh6 = Hh[(192 + q*8 + n)*2];
            uint32_t bl6 = Hl[(192 + q*8 + n)*2];
            mma1688(d4, Ahr[24], Ahr[25], bh6);
            mma1688(d4, Alr[24], Alr[25], bh6);
            mma1688(d4, Ahr[24], Ahr[25], bl6);
        }
        {
            float* pp = ps + g0*8 + q*2;
            *(float2*)pp        = make_float2(d4[0], d4[1]);
            *(float2*)(pp + 64) = make_float2(d4[2], d4[3]);
        }
        __syncthreads();

        if (tid < 400) {
            float gi0 = ps[ h0      *8 + ab] + xv0.x, gi1 = ps[(h0+1)  *8 + ab] + xv0.y;
            float gf0 = ps[(h0+100)*8 + ab] + xv1.x, gf1 = ps[(h0+101)*8 + ab] + xv1.y;
            float gg0 = ps[(h0+200)*8 + ab] + xv2.x, gg1 = ps[(h0+201)*8 + ab] + xv2.y;
            float go0 = ps[(h0+300)*8 + ab] + xv3.x, go1 = ps[(h0+301)*8 + ab] + xv3.y;
            float iv0 = sigf(gi0), fv0 = sigf(gf0), gv0 = tanhfast(gg0), ov0 = sigf(go0);
            float iv1 = sigf(gi1), fv1 = sigf(gf1), gv1 = tanhfast(gg1), ov1 = sigf(go1);
            c0 = fv0*c0 + iv0*gv0;
            c1 = fv1*c1 + iv1*gv1;
            float hv0 = ov0 * tanhfast(c0);
            float hv1 = ov1 * tanhfast(c1);
            unsigned short s0h, s0l, s1h, s1l;
            bfsplit(hv0, s0h, s0l);
            bfsplit(hv1, s1h, s1l);
            uint32_t wh  = (uint32_t)s0h | ((uint32_t)s1h << 16);
            uint32_t wl2 = (uint32_t)s0l | ((uint32_t)s1l << 16);
            Hh[aw] = wh;
            Hl[aw] = wl2;
            if (mode == 0) {
                // fused bf16-split store: layer-1 GEMM A operand word
                size_t row = (size_t)t*BB + b0 + ab;
                size_t col = (size_t)dir*50 + (h0 >> 1);
                Aoh[row*112 + col] = wh;
                Aol[row*112 + col] = wl2;
            } else {
                *(float2*)&hout[((size_t)t*BB + b0 + ab)*200 + dir*100 + h0] = make_float2(hv0, hv1);
            }
        }
    }
}

// ---- emissions -----------------------------------------------------------------
__global__ void __launch_bounds__(256) em_kernel(
    const float* __restrict__ h2, const float* __restrict__ wl,
    const float* __restrict__ bl, float* __restrict__ em)
{
    __shared__ float wls[1600];
    __shared__ float bls[8];
    int tid = threadIdx.x;
    for (int i = tid; i < 1600; i += 256) wls[i] = wl[i];
    if (tid < 8) bls[tid] = bl[tid];
    __syncthreads();
    int warp = tid >> 5, lane = tid & 31;
    size_t row = (size_t)blockIdx.x*8 + warp;
    float acc[8] = {0.f,0.f,0.f,0.f,0.f,0.f,0.f,0.f};
    const float* hr = h2 + row*200;
    #pragma unroll
    for (int i = 0; i < 7; i++) {
        int k = lane + i*32;
        if (k < 200) {
            float x = hr[k];
            #pragma unroll
            for (int gg = 0; gg < 8; gg++) acc[gg] += x * wls[gg*200 + k];
        }
    }
    #pragma unroll
    for (int gg = 0; gg < 8; gg++) {
        float v = acc[gg];
        #pragma unroll
        for (int o = 16; o > 0; o >>= 1) v += __shfl_xor_sync(0xffffffffu, v, o);
        if (lane == 0) em[row*8 + gg] = v + bls[gg];
    }
}

// ---- CRF forward ---------------------------------------------------------------
__global__ void __launch_bounds__(256) crf_fwd(
    const float* __restrict__ em, const int* __restrict__ tags,
    const float* __restrict__ start_t, const float* __restrict__ end_t,
    const float* __restrict__ trans, float* __restrict__ pl)
{
    int tid = blockIdx.x*256 + threadIdx.x;
    int b = tid >> 3, k = tid & 7;
    float trcol[8];
    #pragma unroll
    for (int kk = 0; kk < 8; kk++) trcol[kk] = trans[kk*8 + k];

    float score = start_t[k] + em[(size_t)b*8 + k];

    float nump = 0.f;
    for (int t = 1 + k; t < TT; t += 8) {
        int tp = tags[(t-1)*BB + b];
        int tc = tags[t*BB + b];
        nump += trans[tp*8 + tc] + em[((size_t)t*BB + b)*8 + tc];
    }
    if (k == 0) {
        int t0 = tags[b];
        nump += start_t[t0] + em[(size_t)b*8 + t0] + end_t[tags[(TT-1)*BB + b]];
    }

    for (int t = 1; t < TT; t++) {
        float e = em[((size_t)t*BB + b)*8 + k];
        float v[8];
        float m = -3.4e38f;
        #pragma unroll
        for (int kk = 0; kk < 8; kk++) {
            float s = __shfl_sync(0xffffffffu, score, kk, 8);
            v[kk] = s + trcol[kk];
            m = fmaxf(m, v[kk]);
        }
        float ss = 0.f;
        #pragma unroll
        for (int kk = 0; kk < 8; kk++) ss += expf(v[kk] - m);
        score = m + logf(ss) + e;
    }

    float v = score + end_t[k];
    float m = v;
    #pragma unroll
    for (int kk = 0; kk < 8; kk++) m = fmaxf(m, __shfl_sync(0xffffffffu, v, kk, 8));
    float ex = expf(v - m);
    float ssum = 0.f;
    #pragma unroll
    for (int kk = 0; kk < 8; kk++) ssum += __shfl_sync(0xffffffffu, ex, kk, 8);
    float denom = m + logf(ssum);

    float nsum = 0.f;
    #pragma unroll
    for (int kk = 0; kk < 8; kk++) nsum += __shfl_sync(0xffffffffu, nump, kk, 8);
    if (k == 0) pl[b] = nsum - denom;
}

// ---- Viterbi -------------------------------------------------------------------
__global__ void __launch_bounds__(256) viterbi_k(
    const float* __restrict__ em, const float* __restrict__ start_t,
    const float* __restrict__ end_t, const float* __restrict__ trans,
    unsigned char* __restrict__ hist, float* __restrict__ dec)
{
    int tid = blockIdx.x*256 + threadIdx.x;
    int b = tid >> 3, k = tid & 7;
    float trcol[8];
    #pragma unroll
    for (int kk = 0; kk < 8; kk++) trcol[kk] = trans[kk*8 + k];

    float score = start_t[k] + em[(size_t)b*8 + k];
    for (int t = 1; t < TT; t++) {
        float e = em[((size_t)t*BB + b)*8 + k];
        float best = -3.4e38f;
        int arg = 0;
        #pragma unroll
        for (int kk = 0; kk < 8; kk++) {
            float s = __shfl_sync(0xffffffffu, score, kk, 8) + trcol[kk];
            if (s > best) { best = s; arg = kk; }
        }
        hist[((size_t)(t-1)*BB + b)*8 + k] = (unsigned char)arg;
        score = best + e;
    }
    float v = score + end_t[k];
    float best = -3.4e38f;
    int arg = 0;
    #pragma unroll
    for (int kk = 0; kk < 8; kk++) {
        float s = __shfl_sync(0xffffffffu, v, kk, 8);
        if (s > best) { best = s; arg = kk; }
    }
    __syncwarp();
    if (k == 0) {
        int nxt = arg;
        dec[(size_t)(TT-1)*BB + b] = (float)nxt;
        for (int i = TT - 2; i >= 0; i--) {
            nxt = hist[((size_t)i*BB + b)*8 + nxt];
            dec[(size_t)i*BB + b] = (float)nxt;
        }
    }
}

// ---- deterministic loss reduction ----------------------------------------------
__global__ void loss_reduce(const float* __restrict__ pl, float* __restrict__ out)
{
    __shared__ float s[512];
    int tid = threadIdx.x;
    s[tid] = pl[tid];
    __syncthreads();
    for (int ofs = 256; ofs > 0; ofs >>= 1) {
        if (tid < ofs) s[tid] += s[tid + ofs];
        __syncthreads();
    }
    if (tid == 0) out[0] = s[0];
}

// ---- host launch ---------------------------------------------------------------
extern "C" void kernel_launch(void* const* d_in, const int* in_sizes, int n_in,
                              void* d_out, int out_size)
{
    const int*   sentence = (const int*)d_in[0];
    const int*   tags     = (const int*)d_in[1];
    const float* emb      = (const float*)d_in[3];
    const float* wih0f = (const float*)d_in[4];
    const float* whh0f = (const float*)d_in[5];
    const float* bih0f = (const float*)d_in[6];
    const float* bhh0f = (const float*)d_in[7];
    const float* wih0b = (const float*)d_in[8];
    const float* whh0b = (const float*)d_in[9];
    const float* bih0b = (const float*)d_in[10];
    const float* bhh0b = (const float*)d_in[11];
    const float* wih1f = (const float*)d_in[12];
    const float* whh1f = (const float*)d_in[13];
    const float* bih1f = (const float*)d_in[14];
    const float* bhh1f = (const float*)d_in[15];
    const float* wih1b = (const float*)d_in[16];
    const float* whh1b = (const float*)d_in[17];
    const float* bih1b = (const float*)d_in[18];
    const float* bhh1b = (const float*)d_in[19];
    const float* wl      = (const float*)d_in[20];
    const float* bl      = (const float*)d_in[21];
    const float* start_t = (const float*)d_in[22];
    const float* end_t   = (const float*)d_in[23];
    const float* trans   = (const float*)d_in[24];
    float* out = (float*)d_out;

    void* p;
    cudaGetSymbolAddress(&p, g_Bh0);     uint32_t* pBh0 = (uint32_t*)p;
    cudaGetSymbolAddress(&p, g_Bl0);     uint32_t* pBl0 = (uint32_t*)p;
    cudaGetSymbolAddress(&p, g_Bh1);     uint32_t* pBh1 = (uint32_t*)p;
    cudaGetSymbolAddress(&p, g_Bl1);     uint32_t* pBl1 = (uint32_t*)p;
    cudaGetSymbolAddress(&p, g_b0);      float* pB0   = (float*)p;
    cudaGetSymbolAddress(&p, g_b1);      float* pB1   = (float*)p;
    cudaGetSymbolAddress(&p, g_Wpk_h);   uint32_t* pWph = (uint32_t*)p;
    cudaGetSymbolAddress(&p, g_Wpk_l);   uint32_t* pWpl = (uint32_t*)p;
    cudaGetSymbolAddress(&p, g_A0h);     uint32_t* pA0h = (uint32_t*)p;
    cudaGetSymbolAddress(&p, g_A0l);     uint32_t* pA0l = (uint32_t*)p;
    cudaGetSymbolAddress(&p, g_A1h);     uint32_t* pA1h = (uint32_t*)p;
    cudaGetSymbolAddress(&p, g_A1l);     uint32_t* pA1l = (uint32_t*)p;
    cudaGetSymbolAddress(&p, g_projemb); float* pProj = (float*)p;
    cudaGetSymbolAddress(&p, g_xp1);     float* pXp1  = (float*)p;
    cudaGetSymbolAddress(&p, g_h2);      float* pH2   = (float*)p;
    cudaGetSymbolAddress(&p, g_em);      float* pEm   = (float*)p;
    cudaGetSymbolAddress(&p, g_hist);    unsigned char* pHist = (unsigned char*)p;
    cudaGetSymbolAddress(&p, g_pl);      float* pPl   = (float*)p;

    cudaFuncSetAttribute(mma_gemm, cudaFuncAttributeMaxDynamicSharedMemorySize, GSM_BYTES);

    // all weight prep up front (no bubbles later)
    prep_kernel<<<(800*KPD2_0 + 800*KPD2_1 + 1600 + 255)/256, 256>>>(
        wih0f, wih0b, bih0f, bhh0f, bih0b, bhh0b,
        wih1f, wih1b, bih1f, bhh1f, bih1b, bhh1b);
    prep_whh2<<<(4*400*56 + 255)/256, 256>>>(whh0f, whh0b, whh1f, whh1b, pWph, pWpl);

    {
        size_t tot = (size_t)VV*KPD2_0;
        split_a<<<(unsigned)((tot + 255)/256), 256>>>(emb, pA0h, pA0l, VV, EE, KPD2_0);
    }
    zero_tail<<<(unsigned)(((size_t)NN*12 + 255)/256), 256>>>(pA1h, pA1l);

    mma_gemm<<<dim3(5, (VV + 127)/128), 256, GSM_BYTES>>>(
        pA0h, pA0l, pBh0, pBl0, pB0, pProj, VV, KPD2_0, KPAD0/32);

    // layer 0: writes the layer-1 GEMM A operand directly (fused bf16 split)
    lstm_layer<<<128, 800>>>(pProj, sentence, pWph, pWpl, pH2, pA1h, pA1l, 0);

    mma_gemm<<<dim3(5, NN/128), 256, GSM_BYTES>>>(
        pA1h, pA1l, pBh1, pBl1, pB1, pXp1, NN, KPD2_1, KPAD1/32);

    // layer 1: weights at layer offset 2*22400
    lstm_layer<<<128, 800>>>(pXp1, (const int*)0, pWph + 2*22400, pWpl + 2*22400,
                             pH2, pA1h, pA1l, 1);

    em_kernel<<<NN/8, 256>>>(pH2, wl, bl, pEm);

    crf_fwd<<<BB*KCRF/256, 256>>>(pEm, tags, start_t, end_t, trans, pPl);

    viterbi_k<<<BB*KCRF/256, 256>>>(pEm, start_t, end_t, trans, pHist, out + 1);

    loss_reduce<<<1, 512>>>(pPl, out);
}

// round 15
// speedup vs baseline: 1.0497x; 1.0085x over previous
#include <cuda_runtime.h>
#include <cuda_bf16.h>
#include <math.h>
#include <stdint.h>

#define TT 256
#define BB 512
#define VV 50000
#define EE 300
#define HHH 100
#define KCRF 8
#define NN (TT*BB)

#define KPAD0 320
#define KPD2_0 160
#define KPAD1 224
#define KPD2_1 112

typedef unsigned long long ull;

// ---- helpers -------------------------------------------------------------------
__device__ __forceinline__ float sigf(float x) { return __frcp_rn(1.f + __expf(-x)); }
__device__ __forceinline__ float tanhfast(float x) { return __fmaf_rn(2.f, sigf(2.f*x), -1.f); }

__device__ __forceinline__ unsigned short bfbits(float a) {
    __nv_bfloat16 h = __float2bfloat16_rn(a);
    return *reinterpret_cast<unsigned short*>(&h);
}
__device__ __forceinline__ float bf2f(unsigned short u) {
    __nv_bfloat16 h = *reinterpret_cast<__nv_bfloat16*>(&u);
    return __bfloat162float(h);
}
__device__ __forceinline__ void bfsplit(float v, unsigned short &hi, unsigned short &lo) {
    hi = bfbits(v);
    lo = bfbits(v - bf2f(hi));
}

__device__ __forceinline__ uint32_t smem_u32(const void* p) {
    uint32_t a;
    asm("{ .reg .u64 t; cvta.to.shared.u64 t, %1; cvt.u32.u64 %0, t; }" : "=r"(a) : "l"(p));
    return a;
}
__device__ __forceinline__ void cpa16(uint32_t dst, const void* src) {
    asm volatile("cp.async.cg.shared.global [%0], [%1], 16;" :: "r"(dst), "l"(src));
}
__device__ __forceinline__ void cpa16z(uint32_t dst, const void* src, uint32_t ssz) {
    asm volatile("cp.async.cg.shared.global [%0], [%1], 16, %2;" :: "r"(dst), "l"(src), "r"(ssz));
}
#define CP_COMMIT() asm volatile("cp.async.commit_group;" ::: "memory")
#define CP_WAIT(n)  asm volatile("cp.async.wait_group %0;" :: "n"(n) : "memory")

// ---- mma.sync ------------------------------------------------------------------
__device__ __forceinline__ void mma16816(float d[4], const uint32_t a[4], const uint32_t b[2]) {
    asm volatile("mma.sync.aligned.m16n8k16.row.col.f32.bf16.bf16.f32 "
        "{%0,%1,%2,%3}, {%4,%5,%6,%7}, {%8,%9}, {%0,%1,%2,%3};"
        : "+f"(d[0]), "+f"(d[1]), "+f"(d[2]), "+f"(d[3])
        : "r"(a[0]), "r"(a[1]), "r"(a[2]), "r"(a[3]), "r"(b[0]), "r"(b[1]));
}
__device__ __forceinline__ void mma16816v(float d[4], const uint32_t a[4], uint32_t b0, uint32_t b1) {
    asm volatile("mma.sync.aligned.m16n8k16.row.col.f32.bf16.bf16.f32 "
        "{%0,%1,%2,%3}, {%4,%5,%6,%7}, {%8,%9}, {%0,%1,%2,%3};"
        : "+f"(d[0]), "+f"(d[1]), "+f"(d[2]), "+f"(d[3])
        : "r"(a[0]), "r"(a[1]), "r"(a[2]), "r"(a[3]), "r"(b0), "r"(b1));
}
__device__ __forceinline__ void mma1688(float d[4], uint32_t a0, uint32_t a1, uint32_t b0) {
    asm volatile("mma.sync.aligned.m16n8k8.row.col.f32.bf16.bf16.f32 "
        "{%0,%1,%2,%3}, {%4,%5}, {%6}, {%0,%1,%2,%3};"
        : "+f"(d[0]), "+f"(d[1]), "+f"(d[2]), "+f"(d[3])
        : "r"(a0), "r"(a1), "r"(b0));
}

// ---- scratch -------------------------------------------------------------------
__device__ uint32_t g_Bh0[800*KPD2_0];
__device__ uint32_t g_Bl0[800*KPD2_0];
__device__ uint32_t g_Bh1[800*KPD2_1];
__device__ uint32_t g_Bl1[800*KPD2_1];
__device__ float    g_b0[800];
__device__ float    g_b1[800];
__device__ uint32_t g_Wpk_h[4*400*56];
__device__ uint32_t g_Wpk_l[4*400*56];
__device__ uint32_t g_A0h[(size_t)VV*KPD2_0];
__device__ uint32_t g_A0l[(size_t)VV*KPD2_0];
__device__ uint32_t g_A1h[(size_t)NN*KPD2_1];
__device__ uint32_t g_A1l[(size_t)NN*KPD2_1];
__device__ float    g_projemb[(size_t)VV*800];
__device__ float    g_xp1[(size_t)NN*800];
__device__ float    g_h2[(size_t)NN*200];
__device__ float    g_em[(size_t)NN*KCRF];
__device__ unsigned char g_hist[(size_t)(TT-1)*BB*KCRF];
__device__ float    g_pl[BB];

// ---- weight prep (input-proj weights for GEMM) ---------------------------------
__global__ void prep_kernel(
    const float* __restrict__ wih0f, const float* __restrict__ wih0b,
    const float* __restrict__ bih0f, const float* __restrict__ bhh0f,
    const float* __restrict__ bih0b, const float* __restrict__ bhh0b,
    const float* __restrict__ wih1f, const float* __restrict__ wih1b,
    const float* __restrict__ bih1f, const float* __restrict__ bhh1f,
    const float* __restrict__ bih1b, const float* __restrict__ bhh1b)
{
    int i = blockIdx.x*256 + threadIdx.x;
    if (i < 800*KPD2_0) {
        int n = i / KPD2_0, kk = i % KPD2_0;
        int k0 = 2*kk, k1 = 2*kk + 1;
        float v0 = (k0 < EE) ? ((n < 400) ? wih0f[n*EE + k0] : wih0b[(n-400)*EE + k0]) : 0.f;
        float v1 = (k1 < EE) ? ((n < 400) ? wih0f[n*EE + k1] : wih0b[(n-400)*EE + k1]) : 0.f;
        unsigned short h0, l0, h1, l1;
        bfsplit(v0, h0, l0); bfsplit(v1, h1, l1);
        g_Bh0[i] = (uint32_t)h0 | ((uint32_t)h1 << 16);
        g_Bl0[i] = (uint32_t)l0 | ((uint32_t)l1 << 16);
    } else if (i < 800*KPD2_0 + 800*KPD2_1) {
        int j = i - 800*KPD2_0;
        int n = j / KPD2_1, kk = j % KPD2_1;
        int k0 = 2*kk, k1 = 2*kk + 1;
        float v0 = (k0 < 200) ? ((n < 400) ? wih1f[n*200 + k0] : wih1b[(n-400)*200 + k0]) : 0.f;
        float v1 = (k1 < 200) ? ((n < 400) ? wih1f[n*200 + k1] : wih1b[(n-400)*200 + k1]) : 0.f;
        unsigned short h0, l0, h1, l1;
        bfsplit(v0, h0, l0); bfsplit(v1, h1, l1);
        g_Bh1[j] = (uint32_t)h0 | ((uint32_t)h1 << 16);
        g_Bl1[j] = (uint32_t)l0 | ((uint32_t)l1 << 16);
    } else if (i < 800*KPD2_0 + 800*KPD2_1 + 800) {
        int n = i - (800*KPD2_0 + 800*KPD2_1);
        g_b0[n] = (n < 400) ? (bih0f[n] + bhh0f[n]) : (bih0b[n-400] + bhh0b[n-400]);
    } else if (i < 800*KPD2_0 + 800*KPD2_1 + 1600) {
        int n = i - (800*KPD2_0 + 800*KPD2_1 + 800);
        g_b1[n] = (n < 400) ? (bih1f[n] + bhh1f[n]) : (bih1b[n-400] + bhh1b[n-400]);
    }
}

// ---- whh pack for BOTH layers in one pass --------------------------------------
__global__ void prep_whh2(const float* __restrict__ whh0f, const float* __restrict__ whh0b,
                          const float* __restrict__ whh1f, const float* __restrict__ whh1b,
                          uint32_t* __restrict__ Wh, uint32_t* __restrict__ Wl)
{
    int i = blockIdx.x*256 + threadIdx.x;
    if (i >= 4*400*56) return;
    int ld = i / (2*400*56);
    int rem0 = i - ld*(2*400*56);
    int d = rem0 / (400*56);
    int rem = rem0 - d*(400*56);
    int g = rem / 56, w = rem % 56;
    const float* W = ld ? (d ? whh1b : whh1f) : (d ? whh0b : whh0f);
    int k0 = 2*w, k1 = 2*w + 1;
    float v0 = (k0 < 100) ? W[g*100 + k0] : 0.f;
    float v1 = (k1 < 100) ? W[g*100 + k1] : 0.f;
    unsigned short h0, l0, h1, l1;
    bfsplit(v0, h0, l0); bfsplit(v1, h1, l1);
    Wh[i] = (uint32_t)h0 | ((uint32_t)h1 << 16);
    Wl[i] = (uint32_t)l0 | ((uint32_t)l1 << 16);
}

// ---- A split pass (emb only) ---------------------------------------------------
__global__ void split_a(const float* __restrict__ A, uint32_t* __restrict__ Ah,
                        uint32_t* __restrict__ Al, int M, int K, int kpd2)
{
    size_t i = (size_t)blockIdx.x*256 + threadIdx.x;
    if (i >= (size_t)M*kpd2) return;
    int kk = (int)(i % kpd2);
    size_t r = i / kpd2;
    int k0 = 2*kk, k1 = 2*kk + 1;
    float v0 = (k0 < K) ? A[r*K + k0] : 0.f;
    float v1 = (k1 < K) ? A[r*K + k1] : 0.f;
    unsigned short h0, l0, h1, l1;
    bfsplit(v0, h0, l0); bfsplit(v1, h1, l1);
    Ah[i] = (uint32_t)h0 | ((uint32_t)h1 << 16);
    Al[i] = (uint32_t)l0 | ((uint32_t)l1 << 16);
}

// ---- zero padding cols 100..111 of the layer-1 A operand (one-time) ------------
__global__ void zero_tail(uint32_t* __restrict__ Ah, uint32_t* __restrict__ Al)
{
    size_t i = (size_t)blockIdx.x*256 + threadIdx.x;
    if (i >= (size_t)NN*12) return;
    size_t row = i / 12;
    int cc = 100 + (int)(i % 12);
    Ah[row*112 + cc] = 0;
    Al[row*112 + cc] = 0;
}

// ---- HMMA bf16 3-term GEMM (R8 128x160 — measured best) ------------------------
#define AS_OFF(bf,s,r,q) ((((bf)*2 + (s))*128 + (r))*20 + (q))
#define BS_OFF(bf,s,r,q) (10240 + (((bf)*2 + (s))*160 + (r))*20 + (q))
#define GSM_BYTES (23040*4)

__global__ void __launch_bounds__(256) mma_gemm(
    const uint32_t* __restrict__ Ah, const uint32_t* __restrict__ Al,
    const uint32_t* __restrict__ Bh, const uint32_t* __restrict__ Bl,
    const float* __restrict__ bias, float* __restrict__ C,
    int M, int kpd2, int nc)
{
    extern __shared__ uint32_t s32[];
    const uint32_t sb = smem_u32(s32);
    const int tid = threadIdx.x;
    const int bm  = blockIdx.y * 128;
    const int bn0 = blockIdx.x * 160;
    const int warp = tid >> 5, lane = tid & 31;
    const int wm = (warp & 1) * 64;
    const int wn = (warp >> 1) * 40;
    const int g = lane >> 2, tig = lane & 3;

    float acc[4][5][4];
    #pragma unroll
    for (int mf = 0; mf < 4; mf++)
        #pragma unroll
        for (int nf = 0; nf < 5; nf++)
            #pragma unroll
            for (int c = 0; c < 4; c++) acc[mf][nf][c] = 0.f;

    auto stageA = [&](int ci, int bf) {
        #pragma unroll
        for (int j = 0; j < 4; j++) {
            int idx = tid + 256*j;
            int s = idx >> 9;
            int r = (idx >> 2) & 127;
            int q = idx & 3;
            const uint32_t* base = s ? Al : Ah;
            int row = bm + r;
            const uint32_t* src = (row < M) ? (base + (size_t)row*kpd2 + ci*16 + q*4) : base;
            cpa16z(sb + 4*AS_OFF(bf, s, r, q*4), src, (row < M) ? 16u : 0u);
        }
    };
    auto stageB = [&](int ci, int bf) {
        #pragma unroll
        for (int j = 0; j < 5; j++) {
            int idx = tid + 256*j;
            int s = idx / 640;
            int rem = idx - s*640;
            int r = rem >> 2;
            int q = rem & 3;
            const uint32_t* base = s ? Bl : Bh;
            cpa16(sb + 4*BS_OFF(bf, s, r, q*4), base + (size_t)(bn0 + r)*kpd2 + ci*16 + q*4);
        }
    };

    stageA(0, 0); stageB(0, 0); CP_COMMIT();
    stageA(1, 1); stageB(1, 1); CP_COMMIT();

    for (int ci = 0; ci < nc; ci++) {
        const int bf = ci & 1;
        if (ci + 1 < nc) { CP_WAIT(1); } else { CP_WAIT(0); }
        __syncthreads();

        #pragma unroll
        for (int ks = 0; ks < 2; ks++) {
            const int kb = 8*ks;
            uint32_t aH[4][4], aL[4][4], bH[5][2], bL[5][2];
            #pragma unroll
            for (int mf = 0; mf < 4; mf++) {
                int r0 = wm + mf*16 + g;
                aH[mf][0] = s32[AS_OFF(bf,0,r0,   kb+tig)];
                aH[mf][1] = s32[AS_OFF(bf,0,r0+8, kb+tig)];
                aH[mf][2] = s32[AS_OFF(bf,0,r0,   kb+4+tig)];
                aH[mf][3] = s32[AS_OFF(bf,0,r0+8, kb+4+tig)];
                aL[mf][0] = s32[AS_OFF(bf,1,r0,   kb+tig)];
                aL[mf][1] = s32[AS_OFF(bf,1,r0+8, kb+tig)];
                aL[mf][2] = s32[AS_OFF(bf,1,r0,   kb+4+tig)];
                aL[mf][3] = s32[AS_OFF(bf,1,r0+8, kb+4+tig)];
            }
            #pragma unroll
            for (int nf = 0; nf < 5; nf++) {
                int n = wn + nf*8 + g;
                bH[nf][0] = s32[BS_OFF(bf,0,n, kb+tig)];
                bH[nf][1] = s32[BS_OFF(bf,0,n, kb+4+tig)];
                bL[nf][0] = s32[BS_OFF(bf,1,n, kb+tig)];
                bL[nf][1] = s32[BS_OFF(bf,1,n, kb+4+tig)];
            }
            #pragma unroll
            for (int mf = 0; mf < 4; mf++)
                #pragma unroll
                for (int nf = 0; nf < 5; nf++) {
                    mma16816(acc[mf][nf], aH[mf], bH[nf]);
                    mma16816(acc[mf][nf], aH[mf], bL[nf]);
                    mma16816(acc[mf][nf], aL[mf], bH[nf]);
                }
        }

        if (ci + 2 < nc) {
            __syncthreads();
            stageA(ci + 2, bf); stageB(ci + 2, bf); CP_COMMIT();
        }
    }

    #pragma unroll
    for (int mf = 0; mf < 4; mf++) {
        int r0 = bm + wm + mf*16 + g;
        #pragma unroll
        for (int nf = 0; nf < 5; nf++) {
            int col = bn0 + wn + nf*8 + 2*tig;
            float b0v = bias[col], b1v = bias[col + 1];
            if (r0 < M) {
                float2 o = make_float2(acc[mf][nf][0] + b0v, acc[mf][nf][1] + b1v);
                *(float2*)&C[(size_t)r0*800 + col] = o;
            }
            if (r0 + 8 < M) {
                float2 o = make_float2(acc[mf][nf][2] + b0v, acc[mf][nf][3] + b1v);
                *(float2*)&C[(size_t)(r0 + 8)*800 + col] = o;
            }
        }
    }
}

// ---- HMMA-based persistent BiLSTM recurrence (R13 version) ---------------------
__global__ void __launch_bounds__(800, 1) lstm_layer(
    const float* __restrict__ xsrc, const int* __restrict__ sentence,
    const uint32_t* __restrict__ Wpkh, const uint32_t* __restrict__ Wpkl,
    float* __restrict__ hout, uint32_t* __restrict__ Aoh, uint32_t* __restrict__ Aol,
    int mode)
{
    __shared__ uint32_t Hh[448];
    __shared__ uint32_t Hl[448];
    __shared__ float ps[3200];
    __shared__ int tok_s[8];
    const int tid  = threadIdx.x;
    const int warp = tid >> 5, lane = tid & 31;
    const int q = lane & 3, n = lane >> 2;
    const int dir = blockIdx.x >> 6;
    const int b0  = (blockIdx.x & 63) * 8;
    const int xofs = dir * 400;

    const uint32_t* Wbh = Wpkh + dir*22400;
    const uint32_t* Wbl = Wpkl + dir*22400;
    const int g0 = warp*16 + n;
    uint32_t Ahr[26], Alr[26];
    #pragma unroll
    for (int ks = 0; ks < 6; ks++) {
        Ahr[ks*4+0] = Wbh[ g0    *56 + ks*8 + q];
        Ahr[ks*4+1] = Wbh[(g0+8)*56 + ks*8 + q];
        Ahr[ks*4+2] = Wbh[ g0    *56 + ks*8 + 4 + q];
        Ahr[ks*4+3] = Wbh[(g0+8)*56 + ks*8 + 4 + q];
        Alr[ks*4+0] = Wbl[ g0    *56 + ks*8 + q];
        Alr[ks*4+1] = Wbl[(g0+8)*56 + ks*8 + q];
        Alr[ks*4+2] = Wbl[ g0    *56 + ks*8 + 4 + q];
        Alr[ks*4+3] = Wbl[(g0+8)*56 + ks*8 + 4 + q];
    }
    Ahr[24] = Wbh[g0*56 + 48 + q];  Ahr[25] = Wbh[(g0+8)*56 + 48 + q];
    Alr[24] = Wbl[g0*56 + 48 + q];  Alr[25] = Wbl[(g0+8)*56 + 48 + q];

    for (int i = tid; i < 448; i += 800) { Hh[i] = 0; Hl[i] = 0; }

    const int hh2 = tid >> 3, ab = tid & 7;
    const int h0 = 2*hh2;
    const int aks = h0 >> 4, akk = h0 & 15;
    const int aw = ((aks*4 + ((akk & 7) >> 1))*8 + ab)*2 + (akk >> 3);
    float c0 = 0.f, c1 = 0.f;

    for (int step = 0; step < TT; step++) {
        const int t = dir ? (TT - 1 - step) : step;
        if (mode == 0 && tid < 8) tok_s[tid] = sentence[t*BB + b0 + tid];
        __syncthreads();

        float2 xv0, xv1, xv2, xv3;
        if (tid < 400) {
            const float* xr;
            if (mode == 0) xr = xsrc + (size_t)tok_s[ab]*800 + xofs + h0;
            else           xr = xsrc + ((size_t)t*BB + b0 + ab)*800 + xofs + h0;
            xv0 = *(const float2*)xr;
            xv1 = *(const float2*)(xr + 100);
            xv2 = *(const float2*)(xr + 200);
            xv3 = *(const float2*)(xr + 300);
        }

        float d4[4] = {0.f, 0.f, 0.f, 0.f};
        #pragma unroll
        for (int ks = 0; ks < 6; ks++) {
            uint2 bh = *(const uint2*)&Hh[(ks*32 + q*8 + n)*2];
            uint2 bl = *(const uint2*)&Hl[(ks*32 + q*8 + n)*2];
            mma16816v(d4, &Ahr[ks*4], bh.x, bh.y);
            mma16816v(d4, &Alr[ks*4], bh.x, bh.y);
            mma16816v(d4, &Ahr[ks*4], bl.x, bl.y);
        }
        {
            uint32_t bh6 = Hh[(192 + q*8 + n)*2];
            uint32_t bl6 = Hl[(192 + q*8 + n)*2];
            mma1688(d4, Ahr[24], Ahr[25], bh6);
            mma1688(d4, Alr[24], Alr[25], bh6);
            mma1688(d4, Ahr[24], Ahr[25], bl6);
        }
        {
            float* pp = ps + g0*8 + q*2;
            *(float2*)pp        = make_float2(d4[0], d4[1]);
            *(float2*)(pp + 64) = make_float2(d4[2], d4[3]);
        }
        __syncthreads();

        if (tid < 400) {
            float gi0 = ps[ h0      *8 + ab] + xv0.x, gi1 = ps[(h0+1)  *8 + ab] + xv0.y;
            float gf0 = ps[(h0+100)*8 + ab] + xv1.x, gf1 = ps[(h0+101)*8 + ab] + xv1.y;
            float gg0 = ps[(h0+200)*8 + ab] + xv2.x, gg1 = ps[(h0+201)*8 + ab] + xv2.y;
            float go0 = ps[(h0+300)*8 + ab] + xv3.x, go1 = ps[(h0+301)*8 + ab] + xv3.y;
            float iv0 = sigf(gi0), fv0 = sigf(gf0), gv0 = tanhfast(gg0), ov0 = sigf(go0);
            float iv1 = sigf(gi1), fv1 = sigf(gf1), gv1 = tanhfast(gg1), ov1 = sigf(go1);
            c0 = fv0*c0 + iv0*gv0;
            c1 = fv1*c1 + iv1*gv1;
            float hv0 = ov0 * tanhfast(c0);
            float hv1 = ov1 * tanhfast(c1);
            unsigned short s0h, s0l, s1h, s1l;
            bfsplit(hv0, s0h, s0l);
            bfsplit(hv1, s1h, s1l);
            uint32_t wh  = (uint32_t)s0h | ((uint32_t)s1h << 16);
            uint32_t wl2 = (uint32_t)s0l | ((uint32_t)s1l << 16);
            Hh[aw] = wh;
            Hl[aw] = wl2;
            if (mode == 0) {
                size_t row = (size_t)t*BB + b0 + ab;
                size_t col = (size_t)dir*50 + (h0 >> 1);
                Aoh[row*112 + col] = wh;
                Aol[row*112 + col] = wl2;
            } else {
                *(float2*)&hout[((size_t)t*BB + b0 + ab)*200 + dir*100 + h0] = make_float2(hv0, hv1);
            }
        }
    }
}

// ---- emissions: 4 rows per warp (amortize wl smem load) ------------------------
__global__ void __launch_bounds__(256) em_kernel(
    const float* __restrict__ h2, const float* __restrict__ wl,
    const float* __restrict__ bl, float* __restrict__ em)
{
    __shared__ float wls[1600];
    __shared__ float bls[8];
    int tid = threadIdx.x;
    for (int i = tid; i < 1600; i += 256) wls[i] = wl[i];
    if (tid < 8) bls[tid] = bl[tid];
    __syncthreads();
    int warp = tid >> 5, lane = tid & 31;
    #pragma unroll
    for (int rr = 0; rr < 4; rr++) {
        size_t row = (size_t)blockIdx.x*32 + warp*4 + rr;
        float acc[8] = {0.f,0.f,0.f,0.f,0.f,0.f,0.f,0.f};
        const float* hr = h2 + row*200;
        #pragma unroll
        for (int i = 0; i < 7; i++) {
            int k = lane + i*32;
            if (k < 200) {
                float x = hr[k];
                #pragma unroll
                for (int gg = 0; gg < 8; gg++) acc[gg] += x * wls[gg*200 + k];
            }
        }
        #pragma unroll
        for (int gg = 0; gg < 8; gg++) {
            float v = acc[gg];
            #pragma unroll
            for (int o = 16; o > 0; o >>= 1) v += __shfl_xor_sync(0xffffffffu, v, o);
            if (lane == 0) em[row*8 + gg] = v + bls[gg];
        }
    }
}

// ---- merged CRF forward + Viterbi (shared em loads, independent chains) --------
__global__ void __launch_bounds__(256) crf_vit(
    const float* __restrict__ em, const int* __restrict__ tags,
    const float* __restrict__ start_t, const float* __restrict__ end_t,
    const float* __restrict__ trans, float* __restrict__ pl,
    unsigned char* __restrict__ hist, float* __restrict__ dec)
{
    int tid = blockIdx.x*256 + threadIdx.x;
    int b = tid >> 3, k = tid & 7;
    float trcol[8];
    #pragma unroll
    for (int kk = 0; kk < 8; kk++) trcol[kk] = trans[kk*8 + k];

    float e0 = em[(size_t)b*8 + k];
    float score_c = start_t[k] + e0;    // CRF forward chain
    float score_v = score_c;            // Viterbi chain (identical init)

    // numerator split across lanes
    float nump = 0.f;
    for (int t = 1 + k; t < TT; t += 8) {
        int tp = tags[(t-1)*BB + b];
        int tc = tags[t*BB + b];
        nump += trans[tp*8 + tc] + em[((size_t)t*BB + b)*8 + tc];
    }
    if (k == 0) {
        int t0 = tags[b];
        nump += start_t[t0] + em[(size_t)b*8 + t0] + end_t[tags[(TT-1)*BB + b]];
    }

    for (int t = 1; t < TT; t++) {
        float e = em[((size_t)t*BB + b)*8 + k];
        // CRF logsumexp update
        float v[8];
        float m = -3.4e38f;
        #pragma unroll
        for (int kk = 0; kk < 8; kk++) {
            float s = __shfl_sync(0xffffffffu, score_c, kk, 8);
            v[kk] = s + trcol[kk];
            m = fmaxf(m, v[kk]);
        }
        // Viterbi max/argmax update (independent chain)
        float best = -3.4e38f;
        int arg = 0;
        #pragma unroll
        for (int kk = 0; kk < 8; kk++) {
            float s = __shfl_sync(0xffffffffu, score_v, kk, 8) + trcol[kk];
            if (s > best) { best = s; arg = kk; }
        }
        hist[((size_t)(t-1)*BB + b)*8 + k] = (unsigned char)arg;
        score_v = best + e;

        float ss = 0.f;
        #pragma unroll
        for (int kk = 0; kk < 8; kk++) ss += expf(v[kk] - m);
        score_c = m + logf(ss) + e;
    }

    // CRF denominator
    {
        float v = score_c + end_t[k];
        float m = v;
        #pragma unroll
        for (int kk = 0; kk < 8; kk++) m = fmaxf(m, __shfl_sync(0xffffffffu, v, kk, 8));
        float ex = expf(v - m);
        float ssum = 0.f;
        #pragma unroll
        for (int kk = 0; kk < 8; kk++) ssum += __shfl_sync(0xffffffffu, ex, kk, 8);
        float denom = m + logf(ssum);
        float nsum = 0.f;
        #pragma unroll
        for (int kk = 0; kk < 8; kk++) nsum += __shfl_sync(0xffffffffu, nump, kk, 8);
        if (k == 0) pl[b] = nsum - denom;
    }

    // Viterbi final + backtrack
    {
        float v = score_v + end_t[k];
        float best = -3.4e38f;
        int arg = 0;
        #pragma unroll
        for (int kk = 0; kk < 8; kk++) {
            float s = __shfl_sync(0xffffffffu, v, kk, 8);
            if (s > best) { best = s; arg = kk; }
        }
        __syncwarp();
        if (k == 0) {
            int nxt = arg;
            dec[(size_t)(TT-1)*BB + b] = (float)nxt;
            for (int i = TT - 2; i >= 0; i--) {
                nxt = hist[((size_t)i*BB + b)*8 + nxt];
                dec[(size_t)i*BB + b] = (float)nxt;
            }
        }
    }
}

// ---- deterministic loss reduction ----------------------------------------------
__global__ void loss_reduce(const float* __restrict__ pl, float* __restrict__ out)
{
    __shared__ float s[512];
    int tid = threadIdx.x;
    s[tid] = pl[tid];
    __syncthreads();
    for (int ofs = 256; ofs > 0; ofs >>= 1) {
        if (tid < ofs) s[tid] += s[tid + ofs];
        __syncthreads();
    }
    if (tid == 0) out[0] = s[0];
}

// ---- host launch ---------------------------------------------------------------
extern "C" void kernel_launch(void* const* d_in, const int* in_sizes, int n_in,
                              void* d_out, int out_size)
{
    const int*   sentence = (const int*)d_in[0];
    const int*   tags     = (const int*)d_in[1];
    const float* emb      = (const float*)d_in[3];
    const float* wih0f = (const float*)d_in[4];
    const float* whh0f = (const float*)d_in[5];
    const float* bih0f = (const float*)d_in[6];
    const float* bhh0f = (const float*)d_in[7];
    const float* wih0b = (const float*)d_in[8];
    const float* whh0b = (const float*)d_in[9];
    const float* bih0b = (const float*)d_in[10];
    const float* bhh0b = (const float*)d_in[11];
    const float* wih1f = (const float*)d_in[12];
    const float* whh1f = (const float*)d_in[13];
    const float* bih1f = (const float*)d_in[14];
    const float* bhh1f = (const float*)d_in[15];
    const float* wih1b = (const float*)d_in[16];
    const float* whh1b = (const float*)d_in[17];
    const float* bih1b = (const float*)d_in[18];
    const float* bhh1b = (const float*)d_in[19];
    const float* wl      = (const float*)d_in[20];
    const float* bl      = (const float*)d_in[21];
    const float* start_t = (const float*)d_in[22];
    const float* end_t   = (const float*)d_in[23];
    const float* trans   = (const float*)d_in[24];
    float* out = (float*)d_out;

    void* p;
    cudaGetSymbolAddress(&p, g_Bh0);     uint32_t* pBh0 = (uint32_t*)p;
    cudaGetSymbolAddress(&p, g_Bl0);     uint32_t* pBl0 = (uint32_t*)p;
    cudaGetSymbolAddress(&p, g_Bh1);     uint32_t* pBh1 = (uint32_t*)p;
    cudaGetSymbolAddress(&p, g_Bl1);     uint32_t* pBl1 = (uint32_t*)p;
    cudaGetSymbolAddress(&p, g_b0);      float* pB0   = (float*)p;
    cudaGetSymbolAddress(&p, g_b1);      float* pB1   = (float*)p;
    cudaGetSymbolAddress(&p, g_Wpk_h);   uint32_t* pWph = (uint32_t*)p;
    cudaGetSymbolAddress(&p, g_Wpk_l);   uint32_t* pWpl = (uint32_t*)p;
    cudaGetSymbolAddress(&p, g_A0h);     uint32_t* pA0h = (uint32_t*)p;
    cudaGetSymbolAddress(&p, g_A0l);     uint32_t* pA0l = (uint32_t*)p;
    cudaGetSymbolAddress(&p, g_A1h);     uint32_t* pA1h = (uint32_t*)p;
    cudaGetSymbolAddress(&p, g_A1l);     uint32_t* pA1l = (uint32_t*)p;
    cudaGetSymbolAddress(&p, g_projemb); float* pProj = (float*)p;
    cudaGetSymbolAddress(&p, g_xp1);     float* pXp1  = (float*)p;
    cudaGetSymbolAddress(&p, g_h2);      float* pH2   = (float*)p;
    cudaGetSymbolAddress(&p, g_em);      float* pEm   = (float*)p;
    cudaGetSymbolAddress(&p, g_hist);    unsigned char* pHist = (unsigned char*)p;
    cudaGetSymbolAddress(&p, g_pl);      float* pPl   = (float*)p;

    cudaFuncSetAttribute(mma_gemm, cudaFuncAttributeMaxDynamicSharedMemorySize, GSM_BYTES);

    prep_kernel<<<(800*KPD2_0 + 800*KPD2_1 + 1600 + 255)/256, 256>>>(
        wih0f, wih0b, bih0f, bhh0f, bih0b, bhh0b,
        wih1f, wih1b, bih1f, bhh1f, bih1b, bhh1b);
    prep_whh2<<<(4*400*56 + 255)/256, 256>>>(whh0f, whh0b, whh1f, whh1b, pWph, pWpl);

    {
        size_t tot = (size_t)VV*KPD2_0;
        split_a<<<(unsigned)((tot + 255)/256), 256>>>(emb, pA0h, pA0l, VV, EE, KPD2_0);
    }
    zero_tail<<<(unsigned)(((size_t)NN*12 + 255)/256), 256>>>(pA1h, pA1l);

    mma_gemm<<<dim3(5, (VV + 127)/128), 256, GSM_BYTES>>>(
        pA0h, pA0l, pBh0, pBl0, pB0, pProj, VV, KPD2_0, KPAD0/32);

    lstm_layer<<<128, 800>>>(pProj, sentence, pWph, pWpl, pH2, pA1h, pA1l, 0);

    mma_gemm<<<dim3(5, NN/128), 256, GSM_BYTES>>>(
        pA1h, pA1l, pBh1, pBl1, pB1, pXp1, NN, KPD2_1, KPAD1/32);

    lstm_layer<<<128, 800>>>(pXp1, (const int*)0, pWph + 2*22400, pWpl + 2*22400,
                             pH2, pA1h, pA1l, 1);

    em_kernel<<<NN/32, 256>>>(pH2, wl, bl, pEm);

    crf_vit<<<BB*KCRF/256, 256>>>(pEm, tags, start_t, end_t, trans, pPl, pHist, out + 1);

    loss_reduce<<<1, 512>>>(pPl, out);
}